// round 1
// baseline (speedup 1.0000x reference)
#include <cuda_runtime.h>
#include <math.h>

#define BB 32
#define LL 512
#define DD 1024
#define HH 16
#define HDIM 64
#define EE 8

// ---------------- scratch (device globals; no allocation allowed) ----------------
__device__ float g_q[(size_t)BB * HH * LL * HDIM];   // 64 MB, [B,H,L,hd], RoPE'd
__device__ float g_k[(size_t)BB * HH * LL * HDIM];   // 64 MB
__device__ float g_v[(size_t)BB * HH * LL * HDIM];   // 64 MB
__device__ float g_ao[(size_t)BB * LL * DD];         // 64 MB, attention out [B,L,D]
__device__ float g_cos[LL * 32];
__device__ float g_sin[LL * 32];
__device__ int   g_routes[BB];

// ---------------- RoPE tables ----------------
__global__ void rope_init_kernel() {
    int idx = blockIdx.x * blockDim.x + threadIdx.x;
    if (idx >= LL * 32) return;
    int l = idx >> 5;
    int jp = idx & 31;                 // pair index; even element index = 2*jp
    float inv = 1.0f / powf(10000.0f, (float)(2 * jp) / 64.0f);
    float ang = (float)l * inv;
    g_cos[idx] = cosf(ang);
    g_sin[idx] = sinf(ang);
}

// ---------------- router: mean-pool -> logits -> softmax / argmax ----------------
__global__ void router_kernel(const float* __restrict__ x,
                              const float* __restrict__ rw,
                              const float* __restrict__ rb,
                              float* __restrict__ probs_out,
                              int write_probs) {
    int b = blockIdx.x;
    __shared__ float mean[DD];
    __shared__ float logits[EE];

    for (int d = threadIdx.x; d < DD; d += blockDim.x) {
        const float* xp = x + (size_t)b * LL * DD + d;
        float s = 0.f;
        #pragma unroll 8
        for (int l = 0; l < LL; l++) s += xp[(size_t)l * DD];
        mean[d] = s * (1.0f / (float)LL);
    }
    __syncthreads();

    int w = threadIdx.x >> 5;
    int lane = threadIdx.x & 31;
    if (w < EE) {
        float s = 0.f;
        for (int d = lane; d < DD; d += 32) s += mean[d] * rw[d * EE + w];
        #pragma unroll
        for (int o = 16; o > 0; o >>= 1) s += __shfl_down_sync(0xffffffffu, s, o);
        if (lane == 0) logits[w] = s + rb[w];
    }
    __syncthreads();

    if (threadIdx.x == 0) {
        float m = logits[0]; int arg = 0;
        #pragma unroll
        for (int e = 1; e < EE; e++) if (logits[e] > m) { m = logits[e]; arg = e; }
        float p[EE], sum = 0.f;
        #pragma unroll
        for (int e = 0; e < EE; e++) { p[e] = expf(logits[e] - m); sum += p[e]; }
        if (write_probs) {
            float inv = 1.0f / sum;
            #pragma unroll
            for (int e = 0; e < EE; e++) probs_out[b * EE + e] = p[e] * inv;
        }
        g_routes[b] = arg;
    }
}

// ---------------- routed projection SGEMM (128x128x8 tiles, 8x8 micro) ----------------
// MODE 0: q (RoPE + transpose to [B,H,L,hd])
// MODE 1: k (RoPE + transpose)
// MODE 2: v (transpose only)
// MODE 3: out projection (input g_ao, plain [B,L,D] store to `out`)
template <int MODE>
__global__ void proj_gemm_kernel(const float* __restrict__ X,
                                 const float* __restrict__ Wall,
                                 float* __restrict__ out) {
    __shared__ float As[8][128];
    __shared__ float Bs[8][128];

    const int b = blockIdx.z;
    const float* Xp = (MODE == 3) ? g_ao : X;
    const float* W = Wall + (size_t)g_routes[b] * DD * DD;
    const float* A = Xp + (size_t)b * LL * DD + (size_t)blockIdx.y * 128 * DD;
    const float* Bp = W + blockIdx.x * 128;

    const int tid = threadIdx.x;
    const int tr = tid >> 4;    // 0..15
    const int tc = tid & 15;    // 0..15

    float acc[8][8];
    #pragma unroll
    for (int i = 0; i < 8; i++)
        #pragma unroll
        for (int j = 0; j < 8; j++) acc[i][j] = 0.f;

    const int ar = tid >> 1;                // 0..127
    const int ac4 = (tid & 1) << 2;         // 0 or 4
    const int br = tid >> 5;                // 0..7
    const int bc4 = (tid & 31) << 2;        // 0..124

    for (int k0 = 0; k0 < DD; k0 += 8) {
        float4 av = *(const float4*)(A + (size_t)ar * DD + k0 + ac4);
        As[ac4 + 0][ar] = av.x;
        As[ac4 + 1][ar] = av.y;
        As[ac4 + 2][ar] = av.z;
        As[ac4 + 3][ar] = av.w;
        float4 bv = *(const float4*)(Bp + (size_t)(k0 + br) * DD + bc4);
        *(float4*)&Bs[br][bc4] = bv;
        __syncthreads();

        #pragma unroll
        for (int kk = 0; kk < 8; kk++) {
            float a[8], w[8];
            *(float4*)(a)     = *(const float4*)&As[kk][tr * 8];
            *(float4*)(a + 4) = *(const float4*)&As[kk][tr * 8 + 4];
            *(float4*)(w)     = *(const float4*)&Bs[kk][tc * 8];
            *(float4*)(w + 4) = *(const float4*)&Bs[kk][tc * 8 + 4];
            #pragma unroll
            for (int i = 0; i < 8; i++)
                #pragma unroll
                for (int j = 0; j < 8; j++)
                    acc[i][j] += a[i] * w[j];
        }
        __syncthreads();
    }

    const int l0 = blockIdx.y * 128 + tr * 8;
    const int e0 = blockIdx.x * 128 + tc * 8;

    if (MODE == 0 || MODE == 1) {
        float* dst = (MODE == 0) ? g_q : g_k;
        #pragma unroll
        for (int i = 0; i < 8; i++) {
            int l = l0 + i;
            #pragma unroll
            for (int jp = 0; jp < 4; jp++) {
                int e = e0 + 2 * jp;
                int h = e >> 6;
                int d = e & 63;
                float cs = g_cos[l * 32 + (d >> 1)];
                float sn = g_sin[l * 32 + (d >> 1)];
                float x0 = acc[i][2 * jp];
                float x1 = acc[i][2 * jp + 1];
                size_t o = ((((size_t)b * HH + h) * LL) + l) * HDIM + d;
                dst[o]     = x0 * cs - x1 * sn;
                dst[o + 1] = x1 * cs + x0 * sn;
            }
        }
    } else if (MODE == 2) {
        #pragma unroll
        for (int i = 0; i < 8; i++) {
            int l = l0 + i;
            #pragma unroll
            for (int j = 0; j < 8; j++) {
                int e = e0 + j;
                size_t o = ((((size_t)b * HH + (e >> 6)) * LL) + l) * HDIM + (e & 63);
                g_v[o] = acc[i][j];
            }
        }
    } else {
        #pragma unroll
        for (int i = 0; i < 8; i++) {
            float* op = out + ((size_t)b * LL + (l0 + i)) * DD + e0;
            #pragma unroll
            for (int j = 0; j < 8; j++) op[j] = acc[i][j];
        }
    }
}

// ---------------- flash attention: Br=Bc=64, 256 threads, 4x4 micro ----------------
__global__ void attn_kernel() {
    extern __shared__ float sm[];
    float* Qs = sm;                  // 64*65
    float* Ks = Qs + 64 * 65;        // 64*65
    float* Vs = Ks + 64 * 65;        // 64*65
    float* Ss = Vs + 64 * 65;        // 64*65
    float* mrow = Ss + 64 * 65;      // 64
    float* lrow = mrow + 64;         // 64
    float* crow = lrow + 64;         // 64

    const int bh = blockIdx.y;       // b*H + h
    const int qt = blockIdx.x;       // q tile (0..7)
    const int tid = threadIdx.x;
    const int tr4 = (tid >> 4) * 4;  // row base 0..60
    const int tc4 = (tid & 15) * 4;  // col base 0..60

    const float* qb = g_q + ((size_t)bh * LL + qt * 64) * HDIM;

    // load Q tile
    for (int idx = tid; idx < 1024; idx += 256) {
        int r = idx >> 4;
        int c = (idx & 15) << 2;
        float4 v = *(const float4*)(qb + r * 64 + c);
        Qs[r * 65 + c + 0] = v.x;
        Qs[r * 65 + c + 1] = v.y;
        Qs[r * 65 + c + 2] = v.z;
        Qs[r * 65 + c + 3] = v.w;
    }
    if (tid < 64) { mrow[tid] = -1e30f; lrow[tid] = 0.f; }

    float acc[4][4];
    #pragma unroll
    for (int i = 0; i < 4; i++)
        #pragma unroll
        for (int j = 0; j < 4; j++) acc[i][j] = 0.f;

    __syncthreads();

    for (int jt = 0; jt <= qt; jt++) {
        const float* kb = g_k + ((size_t)bh * LL + jt * 64) * HDIM;
        const float* vb = g_v + ((size_t)bh * LL + jt * 64) * HDIM;
        for (int idx = tid; idx < 1024; idx += 256) {
            int r = idx >> 4;
            int c = (idx & 15) << 2;
            float4 kv = *(const float4*)(kb + r * 64 + c);
            Ks[r * 65 + c + 0] = kv.x;
            Ks[r * 65 + c + 1] = kv.y;
            Ks[r * 65 + c + 2] = kv.z;
            Ks[r * 65 + c + 3] = kv.w;
            float4 vv = *(const float4*)(vb + r * 64 + c);
            Vs[r * 65 + c + 0] = vv.x;
            Vs[r * 65 + c + 1] = vv.y;
            Vs[r * 65 + c + 2] = vv.z;
            Vs[r * 65 + c + 3] = vv.w;
        }
        __syncthreads();

        // S = Q K^T
        float s[4][4];
        #pragma unroll
        for (int i = 0; i < 4; i++)
            #pragma unroll
            for (int j = 0; j < 4; j++) s[i][j] = 0.f;
        #pragma unroll 4
        for (int k = 0; k < 64; k++) {
            float a[4], bb[4];
            #pragma unroll
            for (int i = 0; i < 4; i++) a[i] = Qs[(tr4 + i) * 65 + k];
            #pragma unroll
            for (int j = 0; j < 4; j++) bb[j] = Ks[(tc4 + j) * 65 + k];
            #pragma unroll
            for (int i = 0; i < 4; i++)
                #pragma unroll
                for (int j = 0; j < 4; j++)
                    s[i][j] += a[i] * bb[j];
        }
        const bool diag = (jt == qt);
        #pragma unroll
        for (int i = 0; i < 4; i++)
            #pragma unroll
            for (int j = 0; j < 4; j++) {
                float v = s[i][j] * 0.125f;
                if (diag && (tc4 + j) > (tr4 + i)) v = -1e30f;
                Ss[(tr4 + i) * 65 + tc4 + j] = v;
            }
        __syncthreads();

        // online softmax, one thread per row
        if (tid < 64) {
            int r = tid;
            float mold = mrow[r];
            float mx = mold;
            #pragma unroll 8
            for (int c = 0; c < 64; c++) mx = fmaxf(mx, Ss[r * 65 + c]);
            float cr = expf(mold - mx);
            float sum = 0.f;
            #pragma unroll 8
            for (int c = 0; c < 64; c++) {
                float p = expf(Ss[r * 65 + c] - mx);
                Ss[r * 65 + c] = p;
                sum += p;
            }
            lrow[r] = lrow[r] * cr + sum;
            mrow[r] = mx;
            crow[r] = cr;
        }
        __syncthreads();

        // O = O*corr + P @ V
        #pragma unroll
        for (int i = 0; i < 4; i++) {
            float cr = crow[tr4 + i];
            #pragma unroll
            for (int j = 0; j < 4; j++) acc[i][j] *= cr;
        }
        #pragma unroll 4
        for (int k = 0; k < 64; k++) {
            float p[4], vv[4];
            #pragma unroll
            for (int i = 0; i < 4; i++) p[i] = Ss[(tr4 + i) * 65 + k];
            #pragma unroll
            for (int j = 0; j < 4; j++) vv[j] = Vs[k * 65 + tc4 + j];
            #pragma unroll
            for (int i = 0; i < 4; i++)
                #pragma unroll
                for (int j = 0; j < 4; j++)
                    acc[i][j] += p[i] * vv[j];
        }
        __syncthreads();
    }

    // epilogue: divide by row sum, store to g_ao [B,L,D]
    const int b = bh / HH;
    const int h = bh % HH;
    #pragma unroll
    for (int i = 0; i < 4; i++) {
        int l = qt * 64 + tr4 + i;
        float inv = 1.0f / lrow[tr4 + i];
        float* op = g_ao + ((size_t)b * LL + l) * DD + h * HDIM + tc4;
        #pragma unroll
        for (int j = 0; j < 4; j++) op[j] = acc[i][j] * inv;
    }
}

// ---------------- launch ----------------
extern "C" void kernel_launch(void* const* d_in, const int* in_sizes, int n_in,
                              void* d_out, int out_size) {
    const float* x  = (const float*)d_in[0];
    const float* qw = (const float*)d_in[1];
    const float* kw = (const float*)d_in[2];
    const float* vw = (const float*)d_in[3];
    const float* ow = (const float*)d_in[4];
    const float* rw = (const float*)d_in[5];
    const float* rb = (const float*)d_in[6];
    float* out = (float*)d_out;

    rope_init_kernel<<<(LL * 32 + 255) / 256, 256>>>();

    int write_probs = (out_size >= BB * LL * DD + BB * EE) ? 1 : 0;
    router_kernel<<<BB, 256>>>(x, rw, rb, out + (size_t)BB * LL * DD, write_probs);

    dim3 g(DD / 128, LL / 128, BB);   // (8, 4, 32)
    proj_gemm_kernel<0><<<g, 256>>>(x, qw, nullptr);
    proj_gemm_kernel<1><<<g, 256>>>(x, kw, nullptr);
    proj_gemm_kernel<2><<<g, 256>>>(x, vw, nullptr);

    const int smem = (4 * 64 * 65 + 3 * 64) * sizeof(float);
    cudaFuncSetAttribute(attn_kernel, cudaFuncAttributeMaxDynamicSharedMemorySize, smem);
    attn_kernel<<<dim3(LL / 64, BB * HH), 256, smem>>>();

    proj_gemm_kernel<3><<<g, 256>>>(nullptr, ow, out);
}

// round 3
// speedup vs baseline: 2.3360x; 2.3360x over previous
#include <cuda_runtime.h>
#include <cuda_bf16.h>
#include <cstdint>
#include <math.h>

#define BB 32
#define LL 512
#define DD 1024
#define HH 16
#define HDIM 64
#define EE 8

// ---------------- scratch (device globals; no allocation allowed) ----------------
__device__ float g_q[(size_t)BB * HH * LL * HDIM];   // [B,H,L,hd] RoPE'd
__device__ float g_k[(size_t)BB * HH * LL * HDIM];
__device__ float g_v[(size_t)BB * HH * LL * HDIM];
__device__ float g_ao[(size_t)BB * LL * DD];         // attention out [B,L,D]
__device__ float g_cos[LL * 32];
__device__ float g_sin[LL * 32];
__device__ int   g_routes[BB];

// bf16 hi/lo tiled+swizzled operands
// X/AO tiles: [rt(128)][kc(16)] each 128 rows x 64 cols bf16 (16KB), SW128-swizzled
__device__ __nv_bfloat16 g_xh[(size_t)16384 * 1024];
__device__ __nv_bfloat16 g_xl[(size_t)16384 * 1024];
// W^T tiles: [wsel(4)][e(8)][nt(8)][kc(16)] each 128(n) x 64(k) bf16, SW128-swizzled
__device__ __nv_bfloat16 g_wth[(size_t)4 * 8 * 1024 * 1024];
__device__ __nv_bfloat16 g_wtl[(size_t)4 * 8 * 1024 * 1024];

// ---------------- PTX helpers ----------------
__device__ __forceinline__ uint32_t smem_u32(const void* p) {
    uint32_t a;
    asm("{ .reg .u64 t; cvta.to.shared.u64 t, %1; cvt.u32.u64 %0, t; }" : "=r"(a) : "l"(p));
    return a;
}

#define MBAR_INIT(a, n) \
    asm volatile("mbarrier.init.shared.b64 [%0], %1;" :: "r"(a), "r"((uint32_t)(n)) : "memory")
#define MBAR_EXPECT_TX(a, b) \
    asm volatile("mbarrier.arrive.expect_tx.shared.b64 _, [%0], %1;" :: "r"(a), "r"((uint32_t)(b)) : "memory")

__device__ __forceinline__ void mbar_wait(uint32_t mbar, uint32_t parity) {
    asm volatile(
        "{\n\t.reg .pred P;\n\t"
        "WL_%=:\n\t"
        "mbarrier.try_wait.parity.acquire.cta.shared::cta.b64 P, [%0], %1, 0x989680;\n\t"
        "@P bra.uni WD_%=;\n\t"
        "bra.uni WL_%=;\n\t"
        "WD_%=:\n\t}"
        :: "r"(mbar), "r"(parity) : "memory");
}

__device__ __forceinline__ void bulk_g2s(uint32_t dst, const void* src, uint32_t bytes, uint32_t mbar) {
    asm volatile(
        "cp.async.bulk.shared::cluster.global.mbarrier::complete_tx::bytes [%0], [%1], %2, [%3];"
        :: "r"(dst), "l"(src), "r"(bytes), "r"(mbar) : "memory");
}

__device__ __forceinline__ void ldsm_x4(uint32_t* r, uint32_t a) {
    asm volatile("ldmatrix.sync.aligned.m8n8.x4.shared.b16 {%0,%1,%2,%3}, [%4];"
                 : "=r"(r[0]), "=r"(r[1]), "=r"(r[2]), "=r"(r[3]) : "r"(a));
}
__device__ __forceinline__ void ldsm_x2(uint32_t* r, uint32_t a) {
    asm volatile("ldmatrix.sync.aligned.m8n8.x2.shared.b16 {%0,%1}, [%2];"
                 : "=r"(r[0]), "=r"(r[1]) : "r"(a));
}
__device__ __forceinline__ void mma_bf16(float* d, const uint32_t* a, const uint32_t* b) {
    asm volatile(
        "mma.sync.aligned.m16n8k16.row.col.f32.bf16.bf16.f32 "
        "{%0,%1,%2,%3}, {%4,%5,%6,%7}, {%8,%9}, {%0,%1,%2,%3};"
        : "+f"(d[0]), "+f"(d[1]), "+f"(d[2]), "+f"(d[3])
        : "r"(a[0]), "r"(a[1]), "r"(a[2]), "r"(a[3]), "r"(b[0]), "r"(b[1]));
}

__device__ __forceinline__ uint32_t pack_bf2(__nv_bfloat16 a, __nv_bfloat16 b) {
    return (uint32_t)__bfloat16_as_ushort(a) | ((uint32_t)__bfloat16_as_ushort(b) << 16);
}

// ---------------- RoPE tables ----------------
__global__ void rope_init_kernel() {
    int idx = blockIdx.x * blockDim.x + threadIdx.x;
    if (idx >= LL * 32) return;
    int l = idx >> 5;
    int jp = idx & 31;
    float inv = 1.0f / powf(10000.0f, (float)(2 * jp) / 64.0f);
    float ang = (float)l * inv;
    g_cos[idx] = cosf(ang);
    g_sin[idx] = sinf(ang);
}

// ---------------- router ----------------
__global__ void router_kernel(const float* __restrict__ x,
                              const float* __restrict__ rw,
                              const float* __restrict__ rb,
                              float* __restrict__ probs_out,
                              int write_probs) {
    int b = blockIdx.x;
    __shared__ float mean[DD];
    __shared__ float logits[EE];

    for (int d = threadIdx.x; d < DD; d += blockDim.x) {
        const float* xp = x + (size_t)b * LL * DD + d;
        float s = 0.f;
        #pragma unroll 8
        for (int l = 0; l < LL; l++) s += xp[(size_t)l * DD];
        mean[d] = s * (1.0f / (float)LL);
    }
    __syncthreads();

    int w = threadIdx.x >> 5;
    int lane = threadIdx.x & 31;
    if (w < EE) {
        float s = 0.f;
        for (int d = lane; d < DD; d += 32) s += mean[d] * rw[d * EE + w];
        #pragma unroll
        for (int o = 16; o > 0; o >>= 1) s += __shfl_down_sync(0xffffffffu, s, o);
        if (lane == 0) logits[w] = s + rb[w];
    }
    __syncthreads();

    if (threadIdx.x == 0) {
        float m = logits[0]; int arg = 0;
        #pragma unroll
        for (int e = 1; e < EE; e++) if (logits[e] > m) { m = logits[e]; arg = e; }
        float p[EE], sum = 0.f;
        #pragma unroll
        for (int e = 0; e < EE; e++) { p[e] = expf(logits[e] - m); sum += p[e]; }
        if (write_probs) {
            float inv = 1.0f / sum;
            #pragma unroll
            for (int e = 0; e < EE; e++) probs_out[b * EE + e] = p[e] * inv;
        }
        g_routes[b] = arg;
    }
}

// ---------------- convert X (or AO) -> tiled swizzled bf16 hi/lo ----------------
__global__ void convert_x_kernel(const float* __restrict__ xsrc, int use_ao) {
    const float* src = use_ao ? g_ao : xsrc;
    const int kc = blockIdx.x, rt = blockIdx.y;
    const int t = threadIdx.x;
    const size_t tile_elem = ((size_t)rt * 16 + kc) * 8192;
    char* dh = (char*)(g_xh + tile_elem);
    char* dl = (char*)(g_xl + tile_elem);

    #pragma unroll
    for (int i = 0; i < 4; i++) {
        int u = t + i * 256;             // 0..1023 16B units
        int r = u >> 3, k8 = u & 7;
        const float* p = src + ((size_t)(rt * 128 + r)) * DD + kc * 64 + k8 * 8;
        float4 a = *(const float4*)p;
        float4 b4 = *(const float4*)(p + 4);
        float xs[8] = {a.x, a.y, a.z, a.w, b4.x, b4.y, b4.z, b4.w};
        __nv_bfloat16 hi[8], lo[8];
        #pragma unroll
        for (int j = 0; j < 8; j++) {
            hi[j] = __float2bfloat16(xs[j]);
            lo[j] = __float2bfloat16(xs[j] - __bfloat162float(hi[j]));
        }
        uint32_t off = (uint32_t)(u * 16);
        off ^= (off >> 3) & 0x70;        // SW128
        uint4 hv = make_uint4(pack_bf2(hi[0], hi[1]), pack_bf2(hi[2], hi[3]),
                              pack_bf2(hi[4], hi[5]), pack_bf2(hi[6], hi[7]));
        uint4 lv = make_uint4(pack_bf2(lo[0], lo[1]), pack_bf2(lo[2], lo[3]),
                              pack_bf2(lo[4], lo[5]), pack_bf2(lo[6], lo[7]));
        *(uint4*)(dh + off) = hv;
        *(uint4*)(dl + off) = lv;
    }
}

// ---------------- convert+transpose W -> tiled swizzled bf16 hi/lo ----------------
__global__ void convert_w_kernel(const float* __restrict__ W, int wsel) {
    __shared__ float sm[64][129];
    const int kc = blockIdx.x, nt = blockIdx.y, e = blockIdx.z;
    const int t = threadIdx.x;
    const float* src = W + ((size_t)e * DD + kc * 64) * DD + nt * 128;

    #pragma unroll
    for (int i = 0; i < 8; i++) {
        int idx = t + i * 256;           // 0..2047 float4s
        int kr = idx >> 5, nc = (idx & 31) << 2;
        float4 v = *(const float4*)(src + (size_t)kr * DD + nc);
        sm[kr][nc] = v.x; sm[kr][nc + 1] = v.y; sm[kr][nc + 2] = v.z; sm[kr][nc + 3] = v.w;
    }
    __syncthreads();

    const size_t tile_elem = (((size_t)e * 8 + nt) * 16 + kc) * 8192;
    char* dh = (char*)(g_wth + (size_t)wsel * 8388608 + tile_elem);
    char* dl = (char*)(g_wtl + (size_t)wsel * 8388608 + tile_elem);

    #pragma unroll
    for (int i = 0; i < 4; i++) {
        int u = t + i * 256;             // 0..1023
        int n = u >> 3, k8 = u & 7;
        __nv_bfloat16 hi[8], lo[8];
        #pragma unroll
        for (int j = 0; j < 8; j++) {
            float x = sm[k8 * 8 + j][n];
            hi[j] = __float2bfloat16(x);
            lo[j] = __float2bfloat16(x - __bfloat162float(hi[j]));
        }
        uint32_t off = (uint32_t)(u * 16);
        off ^= (off >> 3) & 0x70;
        uint4 hv = make_uint4(pack_bf2(hi[0], hi[1]), pack_bf2(hi[2], hi[3]),
                              pack_bf2(hi[4], hi[5]), pack_bf2(hi[6], hi[7]));
        uint4 lv = make_uint4(pack_bf2(lo[0], lo[1]), pack_bf2(lo[2], lo[3]),
                              pack_bf2(lo[4], lo[5]), pack_bf2(lo[6], lo[7]));
        *(uint4*)(dh + off) = hv;
        *(uint4*)(dl + off) = lv;
    }
}

// ---------------- HMMA GEMM: CTA tile 128x128, K=1024 in 16 chunks of 64 -------------
// 8 warps in 2(m) x 4(n); warp tile 64x32. 3-stage bulk-copy pipeline.
// MODE 0: q (RoPE epilogue), 1: k (RoPE), 2: v (transpose), 3: out proj (plain store)
template <int MODE>
__global__ void __launch_bounds__(256, 1) hmma_gemm_kernel(float* __restrict__ out) {
    extern __shared__ __align__(1024) char smem[];
    const uint32_t sb = smem_u32(smem);
    const int tid = threadIdx.x;
    const int lane = tid & 31, wid = tid >> 5;
    const int wm = wid >> 2, wn = wid & 3;
    const int nt = blockIdx.x, mt = blockIdx.y, b = blockIdx.z;
    const int e = g_routes[b];

    const uint32_t FULLB = sb;            // 3 mbarriers
    const uint32_t TILES = sb + 1024;     // 3 stages x 64KB

    if (tid == 0) { MBAR_INIT(FULLB, 1); MBAR_INIT(FULLB + 8, 1); MBAR_INIT(FULLB + 16, 1); }
    __syncthreads();

    const size_t a_t0 = ((size_t)(b * 4 + mt) * 16) * 8192;
    const size_t b_t0 = (((size_t)MODE * 8 + e) * 8 + nt) * 16 * 8192;
    const __nv_bfloat16* Ah = g_xh + a_t0;
    const __nv_bfloat16* Al = g_xl + a_t0;
    const __nv_bfloat16* Bh = g_wth + b_t0;
    const __nv_bfloat16* Bl = g_wtl + b_t0;

    auto issue = [&](int c) {
        int s = c % 3;
        uint32_t fb = FULLB + s * 8;
        uint32_t st = TILES + s * 65536;
        MBAR_EXPECT_TX(fb, 65536);
        bulk_g2s(st,         Ah + (size_t)c * 8192, 16384, fb);
        bulk_g2s(st + 16384, Al + (size_t)c * 8192, 16384, fb);
        bulk_g2s(st + 32768, Bh + (size_t)c * 8192, 16384, fb);
        bulk_g2s(st + 49152, Bl + (size_t)c * 8192, 16384, fb);
    };
    if (tid == 0) { issue(0); issue(1); }

    float acc[4][4][4];
    #pragma unroll
    for (int mf = 0; mf < 4; mf++)
        #pragma unroll
        for (int nf = 0; nf < 4; nf++)
            #pragma unroll
            for (int r = 0; r < 4; r++) acc[mf][nf][r] = 0.f;

    // per-lane ldmatrix address components (byte offsets inside a 128x64 bf16 tile)
    const uint32_t a_row  = (uint32_t)(wm * 64 + (lane & 15)) * 128;
    const uint32_t a_koff = (uint32_t)(lane >> 4) * 16;
    const uint32_t b_row  = (uint32_t)(wn * 32 + (lane & 7)) * 128;
    const uint32_t b_koff = (uint32_t)((lane >> 3) & 1) * 16;

    for (int c = 0; c < 16; c++) {
        const int s = c % 3;
        if (tid == 0 && c + 2 < 16) issue(c + 2);
        mbar_wait(FULLB + s * 8, (uint32_t)((c / 3) & 1));
        const uint32_t base = TILES + s * 65536;

        #pragma unroll
        for (int ks = 0; ks < 4; ks++) {
            const uint32_t k0b = (uint32_t)ks * 32;
            uint32_t ah[4][4], al[4][4];
            #pragma unroll
            for (int mf = 0; mf < 4; mf++) {
                uint32_t byt = a_row + (uint32_t)mf * 2048 + a_koff + k0b;
                uint32_t sw = byt ^ ((byt >> 3) & 0x70);
                ldsm_x4(ah[mf], base + sw);
                ldsm_x4(al[mf], base + 16384 + sw);
            }
            uint32_t bh[4][2], bl[4][2];
            #pragma unroll
            for (int nf = 0; nf < 4; nf++) {
                uint32_t byt = b_row + (uint32_t)nf * 1024 + b_koff + k0b;
                uint32_t sw = byt ^ ((byt >> 3) & 0x70);
                ldsm_x2(bh[nf], base + 32768 + sw);
                ldsm_x2(bl[nf], base + 49152 + sw);
            }
            #pragma unroll
            for (int mf = 0; mf < 4; mf++)
                #pragma unroll
                for (int nf = 0; nf < 4; nf++) {
                    mma_bf16(acc[mf][nf], ah[mf], bh[nf]);
                    mma_bf16(acc[mf][nf], ah[mf], bl[nf]);
                    mma_bf16(acc[mf][nf], al[mf], bh[nf]);
                }
        }
        __syncthreads();
    }

    // ---------------- epilogue (fused RoPE / transpose) ----------------
    const int l_base = mt * 128 + wm * 64 + (lane >> 2);
    const int c_base = nt * 128 + wn * 32 + 2 * (lane & 3);

    #pragma unroll
    for (int mf = 0; mf < 4; mf++) {
        #pragma unroll
        for (int rh = 0; rh < 2; rh++) {
            const int l = l_base + mf * 16 + 8 * rh;
            #pragma unroll
            for (int nf = 0; nf < 4; nf++) {
                const int col = c_base + nf * 8;
                float x0 = acc[mf][nf][2 * rh];
                float x1 = acc[mf][nf][2 * rh + 1];
                if (MODE == 3) {
                    float2* dst = (float2*)(out + ((size_t)b * LL + l) * DD + col);
                    *dst = make_float2(x0, x1);
                } else {
                    const int h = col >> 6;
                    const int d = col & 63;
                    float* dstb = ((MODE == 0) ? g_q : (MODE == 1) ? g_k : g_v)
                                  + (((size_t)b * HH + h) * LL + l) * HDIM + d;
                    if (MODE == 2) {
                        *(float2*)dstb = make_float2(x0, x1);
                    } else {
                        const int p = d >> 1;
                        float cs = g_cos[l * 32 + p];
                        float sn = g_sin[l * 32 + p];
                        *(float2*)dstb = make_float2(x0 * cs - x1 * sn,
                                                     x1 * cs + x0 * sn);
                    }
                }
            }
        }
    }
}

// ---------------- flash attention: Br=Bc=64, 256 threads, 4x4 micro ----------------
__global__ void attn_kernel() {
    extern __shared__ float smf[];
    float* Qs = smf;
    float* Ks = Qs + 64 * 65;
    float* Vs = Ks + 64 * 65;
    float* Ss = Vs + 64 * 65;
    float* mrow = Ss + 64 * 65;
    float* lrow = mrow + 64;
    float* crow = lrow + 64;

    const int bh = blockIdx.y;
    const int qt = blockIdx.x;
    const int tid = threadIdx.x;
    const int tr4 = (tid >> 4) * 4;
    const int tc4 = (tid & 15) * 4;

    const float* qb = g_q + ((size_t)bh * LL + qt * 64) * HDIM;

    for (int idx = tid; idx < 1024; idx += 256) {
        int r = idx >> 4;
        int c = (idx & 15) << 2;
        float4 v = *(const float4*)(qb + r * 64 + c);
        Qs[r * 65 + c + 0] = v.x; Qs[r * 65 + c + 1] = v.y;
        Qs[r * 65 + c + 2] = v.z; Qs[r * 65 + c + 3] = v.w;
    }
    if (tid < 64) { mrow[tid] = -1e30f; lrow[tid] = 0.f; }

    float acc[4][4];
    #pragma unroll
    for (int i = 0; i < 4; i++)
        #pragma unroll
        for (int j = 0; j < 4; j++) acc[i][j] = 0.f;

    __syncthreads();

    for (int jt = 0; jt <= qt; jt++) {
        const float* kb = g_k + ((size_t)bh * LL + jt * 64) * HDIM;
        const float* vb = g_v + ((size_t)bh * LL + jt * 64) * HDIM;
        for (int idx = tid; idx < 1024; idx += 256) {
            int r = idx >> 4;
            int c = (idx & 15) << 2;
            float4 kv = *(const float4*)(kb + r * 64 + c);
            Ks[r * 65 + c + 0] = kv.x; Ks[r * 65 + c + 1] = kv.y;
            Ks[r * 65 + c + 2] = kv.z; Ks[r * 65 + c + 3] = kv.w;
            float4 vv = *(const float4*)(vb + r * 64 + c);
            Vs[r * 65 + c + 0] = vv.x; Vs[r * 65 + c + 1] = vv.y;
            Vs[r * 65 + c + 2] = vv.z; Vs[r * 65 + c + 3] = vv.w;
        }
        __syncthreads();

        float s[4][4];
        #pragma unroll
        for (int i = 0; i < 4; i++)
            #pragma unroll
            for (int j = 0; j < 4; j++) s[i][j] = 0.f;
        #pragma unroll 4
        for (int k = 0; k < 64; k++) {
            float a[4], bb[4];
            #pragma unroll
            for (int i = 0; i < 4; i++) a[i] = Qs[(tr4 + i) * 65 + k];
            #pragma unroll
            for (int j = 0; j < 4; j++) bb[j] = Ks[(tc4 + j) * 65 + k];
            #pragma unroll
            for (int i = 0; i < 4; i++)
                #pragma unroll
                for (int j = 0; j < 4; j++)
                    s[i][j] += a[i] * bb[j];
        }
        const bool diag = (jt == qt);
        #pragma unroll
        for (int i = 0; i < 4; i++)
            #pragma unroll
            for (int j = 0; j < 4; j++) {
                float v = s[i][j] * 0.125f;
                if (diag && (tc4 + j) > (tr4 + i)) v = -1e30f;
                Ss[(tr4 + i) * 65 + tc4 + j] = v;
            }
        __syncthreads();

        if (tid < 64) {
            int r = tid;
            float mold = mrow[r];
            float mx = mold;
            #pragma unroll 8
            for (int c = 0; c < 64; c++) mx = fmaxf(mx, Ss[r * 65 + c]);
            float cr = expf(mold - mx);
            float sum = 0.f;
            #pragma unroll 8
            for (int c = 0; c < 64; c++) {
                float p = expf(Ss[r * 65 + c] - mx);
                Ss[r * 65 + c] = p;
                sum += p;
            }
            lrow[r] = lrow[r] * cr + sum;
            mrow[r] = mx;
            crow[r] = cr;
        }
        __syncthreads();

        #pragma unroll
        for (int i = 0; i < 4; i++) {
            float cr = crow[tr4 + i];
            #pragma unroll
            for (int j = 0; j < 4; j++) acc[i][j] *= cr;
        }
        #pragma unroll 4
        for (int k = 0; k < 64; k++) {
            float p[4], vv[4];
            #pragma unroll
            for (int i = 0; i < 4; i++) p[i] = Ss[(tr4 + i) * 65 + k];
            #pragma unroll
            for (int j = 0; j < 4; j++) vv[j] = Vs[k * 65 + tc4 + j];
            #pragma unroll
            for (int i = 0; i < 4; i++)
                #pragma unroll
                for (int j = 0; j < 4; j++)
                    acc[i][j] += p[i] * vv[j];
        }
        __syncthreads();
    }

    const int b = bh / HH;
    const int h = bh % HH;
    #pragma unroll
    for (int i = 0; i < 4; i++) {
        int l = qt * 64 + tr4 + i;
        float inv = 1.0f / lrow[tr4 + i];
        float* op = g_ao + ((size_t)b * LL + l) * DD + h * HDIM + tc4;
        #pragma unroll
        for (int j = 0; j < 4; j++) op[j] = acc[i][j] * inv;
    }
}

// ---------------- launch ----------------
extern "C" void kernel_launch(void* const* d_in, const int* in_sizes, int n_in,
                              void* d_out, int out_size) {
    const float* x  = (const float*)d_in[0];
    const float* qw = (const float*)d_in[1];
    const float* kw = (const float*)d_in[2];
    const float* vw = (const float*)d_in[3];
    const float* ow = (const float*)d_in[4];
    const float* rw = (const float*)d_in[5];
    const float* rb = (const float*)d_in[6];
    float* out = (float*)d_out;

    const int GEMM_SMEM = 1024 + 3 * 65536;   // 197632
    cudaFuncSetAttribute(hmma_gemm_kernel<0>, cudaFuncAttributeMaxDynamicSharedMemorySize, GEMM_SMEM);
    cudaFuncSetAttribute(hmma_gemm_kernel<1>, cudaFuncAttributeMaxDynamicSharedMemorySize, GEMM_SMEM);
    cudaFuncSetAttribute(hmma_gemm_kernel<2>, cudaFuncAttributeMaxDynamicSharedMemorySize, GEMM_SMEM);
    cudaFuncSetAttribute(hmma_gemm_kernel<3>, cudaFuncAttributeMaxDynamicSharedMemorySize, GEMM_SMEM);

    rope_init_kernel<<<(LL * 32 + 255) / 256, 256>>>();

    int write_probs = (out_size >= BB * LL * DD + BB * EE) ? 1 : 0;
    router_kernel<<<BB, 256>>>(x, rw, rb, out + (size_t)BB * LL * DD, write_probs);

    convert_x_kernel<<<dim3(16, 128), 256>>>(x, 0);
    convert_w_kernel<<<dim3(16, 8, 8), 256>>>(qw, 0);
    convert_w_kernel<<<dim3(16, 8, 8), 256>>>(kw, 1);
    convert_w_kernel<<<dim3(16, 8, 8), 256>>>(vw, 2);
    convert_w_kernel<<<dim3(16, 8, 8), 256>>>(ow, 3);

    dim3 g(DD / 128, LL / 128, BB);   // (8, 4, 32)
    hmma_gemm_kernel<0><<<g, 256, GEMM_SMEM>>>(nullptr);
    hmma_gemm_kernel<1><<<g, 256, GEMM_SMEM>>>(nullptr);
    hmma_gemm_kernel<2><<<g, 256, GEMM_SMEM>>>(nullptr);

    const int ATTN_SMEM = (4 * 64 * 65 + 3 * 64) * sizeof(float);
    cudaFuncSetAttribute(attn_kernel, cudaFuncAttributeMaxDynamicSharedMemorySize, ATTN_SMEM);
    attn_kernel<<<dim3(LL / 64, BB * HH), 256, ATTN_SMEM>>>();

    convert_x_kernel<<<dim3(16, 128), 256>>>(nullptr, 1);   // AO -> bf16 hi/lo
    hmma_gemm_kernel<3><<<g, 256, GEMM_SMEM>>>(out);
}

// round 4
// speedup vs baseline: 3.2402x; 1.3871x over previous
#include <cuda_runtime.h>
#include <cuda_bf16.h>
#include <cstdint>
#include <math.h>

#define BB 32
#define LL 512
#define DD 1024
#define HH 16
#define HDIM 64
#define EE 8

// ---------------- scratch (device globals; no allocation allowed) ----------------
__device__ float g_cos[LL * 32];
__device__ float g_sin[LL * 32];
__device__ int   g_routes[BB];

// X/AO tiles: [rt(128)][kc(16)] each 128 rows x 64 cols bf16 (16KB), SW128-swizzled
__device__ __nv_bfloat16 g_xh[(size_t)16384 * 1024];
__device__ __nv_bfloat16 g_xl[(size_t)16384 * 1024];
// W^T tiles: [wsel(4)][e(8)][nt(8)][kc(16)] each 128(n) x 64(k) bf16, SW128-swizzled
__device__ __nv_bfloat16 g_wth[(size_t)4 * 8 * 1024 * 1024];
__device__ __nv_bfloat16 g_wtl[(size_t)4 * 8 * 1024 * 1024];
// q/k/v bf16 hi/lo: [B*H][512][64], SW128-swizzled 128B rows
__device__ __nv_bfloat16 g_qh[(size_t)BB * HH * LL * HDIM];
__device__ __nv_bfloat16 g_ql[(size_t)BB * HH * LL * HDIM];
__device__ __nv_bfloat16 g_kh[(size_t)BB * HH * LL * HDIM];
__device__ __nv_bfloat16 g_kl[(size_t)BB * HH * LL * HDIM];
__device__ __nv_bfloat16 g_vh[(size_t)BB * HH * LL * HDIM];
__device__ __nv_bfloat16 g_vl[(size_t)BB * HH * LL * HDIM];

// ---------------- PTX helpers ----------------
__device__ __forceinline__ uint32_t smem_u32(const void* p) {
    uint32_t a;
    asm("{ .reg .u64 t; cvta.to.shared.u64 t, %1; cvt.u32.u64 %0, t; }" : "=r"(a) : "l"(p));
    return a;
}

#define MBAR_INIT(a, n) \
    asm volatile("mbarrier.init.shared.b64 [%0], %1;" :: "r"(a), "r"((uint32_t)(n)) : "memory")
#define MBAR_EXPECT_TX(a, b) \
    asm volatile("mbarrier.arrive.expect_tx.shared.b64 _, [%0], %1;" :: "r"(a), "r"((uint32_t)(b)) : "memory")

__device__ __forceinline__ void mbar_wait(uint32_t mbar, uint32_t parity) {
    asm volatile(
        "{\n\t.reg .pred P;\n\t"
        "WL_%=:\n\t"
        "mbarrier.try_wait.parity.acquire.cta.shared::cta.b64 P, [%0], %1, 0x989680;\n\t"
        "@P bra.uni WD_%=;\n\t"
        "bra.uni WL_%=;\n\t"
        "WD_%=:\n\t}"
        :: "r"(mbar), "r"(parity) : "memory");
}

__device__ __forceinline__ void bulk_g2s(uint32_t dst, const void* src, uint32_t bytes, uint32_t mbar) {
    asm volatile(
        "cp.async.bulk.shared::cluster.global.mbarrier::complete_tx::bytes [%0], [%1], %2, [%3];"
        :: "r"(dst), "l"(src), "r"(bytes), "r"(mbar) : "memory");
}

__device__ __forceinline__ void ldsm_x4(uint32_t* r, uint32_t a) {
    asm volatile("ldmatrix.sync.aligned.m8n8.x4.shared.b16 {%0,%1,%2,%3}, [%4];"
                 : "=r"(r[0]), "=r"(r[1]), "=r"(r[2]), "=r"(r[3]) : "r"(a));
}
__device__ __forceinline__ void ldsm_x4t(uint32_t* r, uint32_t a) {
    asm volatile("ldmatrix.sync.aligned.m8n8.x4.trans.shared.b16 {%0,%1,%2,%3}, [%4];"
                 : "=r"(r[0]), "=r"(r[1]), "=r"(r[2]), "=r"(r[3]) : "r"(a));
}
__device__ __forceinline__ void ldsm_x2(uint32_t* r, uint32_t a) {
    asm volatile("ldmatrix.sync.aligned.m8n8.x2.shared.b16 {%0,%1}, [%2];"
                 : "=r"(r[0]), "=r"(r[1]) : "r"(a));
}
__device__ __forceinline__ void mma_bf16(float* d, const uint32_t* a, const uint32_t* b) {
    asm volatile(
        "mma.sync.aligned.m16n8k16.row.col.f32.bf16.bf16.f32 "
        "{%0,%1,%2,%3}, {%4,%5,%6,%7}, {%8,%9}, {%0,%1,%2,%3};"
        : "+f"(d[0]), "+f"(d[1]), "+f"(d[2]), "+f"(d[3])
        : "r"(a[0]), "r"(a[1]), "r"(a[2]), "r"(a[3]), "r"(b[0]), "r"(b[1]));
}

__device__ __forceinline__ uint32_t pack_bf2(__nv_bfloat16 a, __nv_bfloat16 b) {
    return (uint32_t)__bfloat16_as_ushort(a) | ((uint32_t)__bfloat16_as_ushort(b) << 16);
}

// ---------------- RoPE tables ----------------
__global__ void rope_init_kernel() {
    int idx = blockIdx.x * blockDim.x + threadIdx.x;
    if (idx >= LL * 32) return;
    int l = idx >> 5;
    int jp = idx & 31;
    float inv = 1.0f / powf(10000.0f, (float)(2 * jp) / 64.0f);
    float ang = (float)l * inv;
    g_cos[idx] = cosf(ang);
    g_sin[idx] = sinf(ang);
}

// ---------------- router ----------------
__global__ void router_kernel(const float* __restrict__ x,
                              const float* __restrict__ rw,
                              const float* __restrict__ rb,
                              float* __restrict__ probs_out,
                              int write_probs) {
    int b = blockIdx.x;
    __shared__ float mean[DD];
    __shared__ float logits[EE];

    for (int d = threadIdx.x; d < DD; d += blockDim.x) {
        const float* xp = x + (size_t)b * LL * DD + d;
        float s = 0.f;
        #pragma unroll 8
        for (int l = 0; l < LL; l++) s += xp[(size_t)l * DD];
        mean[d] = s * (1.0f / (float)LL);
    }
    __syncthreads();

    int w = threadIdx.x >> 5;
    int lane = threadIdx.x & 31;
    if (w < EE) {
        float s = 0.f;
        for (int d = lane; d < DD; d += 32) s += mean[d] * rw[d * EE + w];
        #pragma unroll
        for (int o = 16; o > 0; o >>= 1) s += __shfl_down_sync(0xffffffffu, s, o);
        if (lane == 0) logits[w] = s + rb[w];
    }
    __syncthreads();

    if (threadIdx.x == 0) {
        float m = logits[0]; int arg = 0;
        #pragma unroll
        for (int e = 1; e < EE; e++) if (logits[e] > m) { m = logits[e]; arg = e; }
        float p[EE], sum = 0.f;
        #pragma unroll
        for (int e = 0; e < EE; e++) { p[e] = expf(logits[e] - m); sum += p[e]; }
        if (write_probs) {
            float inv = 1.0f / sum;
            #pragma unroll
            for (int e = 0; e < EE; e++) probs_out[b * EE + e] = p[e] * inv;
        }
        g_routes[b] = arg;
    }
}

// ---------------- convert X -> tiled swizzled bf16 hi/lo ----------------
__global__ void convert_x_kernel(const float* __restrict__ src) {
    const int kc = blockIdx.x, rt = blockIdx.y;
    const int t = threadIdx.x;
    const size_t tile_elem = ((size_t)rt * 16 + kc) * 8192;
    char* dh = (char*)(g_xh + tile_elem);
    char* dl = (char*)(g_xl + tile_elem);

    #pragma unroll
    for (int i = 0; i < 4; i++) {
        int u = t + i * 256;             // 0..1023 16B units
        int r = u >> 3, k8 = u & 7;
        const float* p = src + ((size_t)(rt * 128 + r)) * DD + kc * 64 + k8 * 8;
        float4 a = *(const float4*)p;
        float4 b4 = *(const float4*)(p + 4);
        float xs[8] = {a.x, a.y, a.z, a.w, b4.x, b4.y, b4.z, b4.w};
        __nv_bfloat16 hi[8], lo[8];
        #pragma unroll
        for (int j = 0; j < 8; j++) {
            hi[j] = __float2bfloat16(xs[j]);
            lo[j] = __float2bfloat16(xs[j] - __bfloat162float(hi[j]));
        }
        uint32_t off = (uint32_t)(u * 16);
        off ^= (off >> 3) & 0x70;        // SW128
        uint4 hv = make_uint4(pack_bf2(hi[0], hi[1]), pack_bf2(hi[2], hi[3]),
                              pack_bf2(hi[4], hi[5]), pack_bf2(hi[6], hi[7]));
        uint4 lv = make_uint4(pack_bf2(lo[0], lo[1]), pack_bf2(lo[2], lo[3]),
                              pack_bf2(lo[4], lo[5]), pack_bf2(lo[6], lo[7]));
        *(uint4*)(dh + off) = hv;
        *(uint4*)(dl + off) = lv;
    }
}

// ---------------- convert+transpose W -> tiled swizzled bf16 hi/lo ----------------
__global__ void convert_w_kernel(const float* __restrict__ W, int wsel) {
    __shared__ float sm[64][129];
    const int kc = blockIdx.x, nt = blockIdx.y, e = blockIdx.z;
    const int t = threadIdx.x;
    const float* src = W + ((size_t)e * DD + kc * 64) * DD + nt * 128;

    #pragma unroll
    for (int i = 0; i < 8; i++) {
        int idx = t + i * 256;           // 0..2047 float4s
        int kr = idx >> 5, nc = (idx & 31) << 2;
        float4 v = *(const float4*)(src + (size_t)kr * DD + nc);
        sm[kr][nc] = v.x; sm[kr][nc + 1] = v.y; sm[kr][nc + 2] = v.z; sm[kr][nc + 3] = v.w;
    }
    __syncthreads();

    const size_t tile_elem = (((size_t)e * 8 + nt) * 16 + kc) * 8192;
    char* dh = (char*)(g_wth + (size_t)wsel * 8388608 + tile_elem);
    char* dl = (char*)(g_wtl + (size_t)wsel * 8388608 + tile_elem);

    #pragma unroll
    for (int i = 0; i < 4; i++) {
        int u = t + i * 256;             // 0..1023
        int n = u >> 3, k8 = u & 7;
        __nv_bfloat16 hi[8], lo[8];
        #pragma unroll
        for (int j = 0; j < 8; j++) {
            float x = sm[k8 * 8 + j][n];
            hi[j] = __float2bfloat16(x);
            lo[j] = __float2bfloat16(x - __bfloat162float(hi[j]));
        }
        uint32_t off = (uint32_t)(u * 16);
        off ^= (off >> 3) & 0x70;
        uint4 hv = make_uint4(pack_bf2(hi[0], hi[1]), pack_bf2(hi[2], hi[3]),
                              pack_bf2(hi[4], hi[5]), pack_bf2(hi[6], hi[7]));
        uint4 lv = make_uint4(pack_bf2(lo[0], lo[1]), pack_bf2(lo[2], lo[3]),
                              pack_bf2(lo[4], lo[5]), pack_bf2(lo[6], lo[7]));
        *(uint4*)(dh + off) = hv;
        *(uint4*)(dl + off) = lv;
    }
}

// ---------------- HMMA GEMM: CTA tile 128x128, K=1024 in 16 chunks of 64 -------------
// 8 warps in 2(m) x 4(n); warp tile 64x32. 3-stage bulk-copy pipeline.
// MODE 0: q (RoPE, bf16 hi/lo out), 1: k (RoPE, hi/lo), 2: v (hi/lo), 3: out proj (fp32)
template <int MODE>
__global__ void __launch_bounds__(256, 1) hmma_gemm_kernel(float* __restrict__ out) {
    extern __shared__ __align__(1024) char smem[];
    const uint32_t sb = smem_u32(smem);
    const int tid = threadIdx.x;
    const int lane = tid & 31, wid = tid >> 5;
    const int wm = wid >> 2, wn = wid & 3;
    const int nt = blockIdx.x, mt = blockIdx.y, b = blockIdx.z;
    const int e = g_routes[b];

    const uint32_t FULLB = sb;            // 3 mbarriers
    const uint32_t TILES = sb + 1024;     // 3 stages x 64KB

    if (tid == 0) { MBAR_INIT(FULLB, 1); MBAR_INIT(FULLB + 8, 1); MBAR_INIT(FULLB + 16, 1); }
    __syncthreads();

    const size_t a_t0 = ((size_t)(b * 4 + mt) * 16) * 8192;
    const size_t b_t0 = (((size_t)MODE * 8 + e) * 8 + nt) * 16 * 8192;
    const __nv_bfloat16* Ah = g_xh + a_t0;
    const __nv_bfloat16* Al = g_xl + a_t0;
    const __nv_bfloat16* Bh = g_wth + b_t0;
    const __nv_bfloat16* Bl = g_wtl + b_t0;

    auto issue = [&](int c) {
        int s = c % 3;
        uint32_t fb = FULLB + s * 8;
        uint32_t st = TILES + s * 65536;
        MBAR_EXPECT_TX(fb, 65536);
        bulk_g2s(st,         Ah + (size_t)c * 8192, 16384, fb);
        bulk_g2s(st + 16384, Al + (size_t)c * 8192, 16384, fb);
        bulk_g2s(st + 32768, Bh + (size_t)c * 8192, 16384, fb);
        bulk_g2s(st + 49152, Bl + (size_t)c * 8192, 16384, fb);
    };
    if (tid == 0) { issue(0); issue(1); }

    float acc[4][4][4];
    #pragma unroll
    for (int mf = 0; mf < 4; mf++)
        #pragma unroll
        for (int nf = 0; nf < 4; nf++)
            #pragma unroll
            for (int r = 0; r < 4; r++) acc[mf][nf][r] = 0.f;

    const uint32_t a_row  = (uint32_t)(wm * 64 + (lane & 15)) * 128;
    const uint32_t a_koff = (uint32_t)(lane >> 4) * 16;
    const uint32_t b_row  = (uint32_t)(wn * 32 + (lane & 7)) * 128;
    const uint32_t b_koff = (uint32_t)((lane >> 3) & 1) * 16;

    for (int c = 0; c < 16; c++) {
        const int s = c % 3;
        if (tid == 0 && c + 2 < 16) issue(c + 2);
        mbar_wait(FULLB + s * 8, (uint32_t)((c / 3) & 1));
        const uint32_t base = TILES + s * 65536;

        #pragma unroll
        for (int ks = 0; ks < 4; ks++) {
            const uint32_t k0b = (uint32_t)ks * 32;
            uint32_t ah[4][4], al[4][4];
            #pragma unroll
            for (int mf = 0; mf < 4; mf++) {
                uint32_t byt = a_row + (uint32_t)mf * 2048 + a_koff + k0b;
                uint32_t sw = byt ^ ((byt >> 3) & 0x70);
                ldsm_x4(ah[mf], base + sw);
                ldsm_x4(al[mf], base + 16384 + sw);
            }
            uint32_t bh[4][2], bl[4][2];
            #pragma unroll
            for (int nf = 0; nf < 4; nf++) {
                uint32_t byt = b_row + (uint32_t)nf * 1024 + b_koff + k0b;
                uint32_t sw = byt ^ ((byt >> 3) & 0x70);
                ldsm_x2(bh[nf], base + 32768 + sw);
                ldsm_x2(bl[nf], base + 49152 + sw);
            }
            #pragma unroll
            for (int mf = 0; mf < 4; mf++)
                #pragma unroll
                for (int nf = 0; nf < 4; nf++) {
                    mma_bf16(acc[mf][nf], ah[mf], bh[nf]);
                    mma_bf16(acc[mf][nf], ah[mf], bl[nf]);
                    mma_bf16(acc[mf][nf], al[mf], bh[nf]);
                }
        }
        __syncthreads();
    }

    // ---------------- epilogue ----------------
    const int l_base = mt * 128 + wm * 64 + (lane >> 2);
    const int c_base = nt * 128 + wn * 32 + 2 * (lane & 3);

    #pragma unroll
    for (int mf = 0; mf < 4; mf++) {
        #pragma unroll
        for (int rh = 0; rh < 2; rh++) {
            const int l = l_base + mf * 16 + 8 * rh;
            #pragma unroll
            for (int nf = 0; nf < 4; nf++) {
                const int col = c_base + nf * 8;
                float x0 = acc[mf][nf][2 * rh];
                float x1 = acc[mf][nf][2 * rh + 1];
                if (MODE == 3) {
                    float2* dst = (float2*)(out + ((size_t)b * LL + l) * DD + col);
                    *dst = make_float2(x0, x1);
                } else {
                    const int h2 = col >> 6;
                    const int d = col & 63;
                    float y0, y1;
                    if (MODE == 2) { y0 = x0; y1 = x1; }
                    else {
                        const int p = d >> 1;
                        float cs = g_cos[l * 32 + p];
                        float sn = g_sin[l * 32 + p];
                        y0 = x0 * cs - x1 * sn;
                        y1 = x1 * cs + x0 * sn;
                    }
                    __nv_bfloat16 hb0 = __float2bfloat16(y0);
                    __nv_bfloat16 hb1 = __float2bfloat16(y1);
                    __nv_bfloat16 lb0 = __float2bfloat16(y0 - __bfloat162float(hb0));
                    __nv_bfloat16 lb1 = __float2bfloat16(y1 - __bfloat162float(hb1));
                    uint32_t off = (uint32_t)((((b * HH + h2) * LL) + l) * 128 + d * 2);
                    uint32_t sw = off ^ ((off >> 3) & 0x70);
                    char* bhp = (char*)((MODE == 0) ? g_qh : (MODE == 1) ? g_kh : g_vh);
                    char* blp = (char*)((MODE == 0) ? g_ql : (MODE == 1) ? g_kl : g_vl);
                    *(uint32_t*)(bhp + sw) = pack_bf2(hb0, hb1);
                    *(uint32_t*)(blp + sw) = pack_bf2(lb0, lb1);
                }
            }
        }
    }
}

// ---------------- flash attention on HMMA: 128 q-rows/CTA, 8 warps x 16 rows ---------
__global__ void __launch_bounds__(256, 2) attn_kernel() {
    extern __shared__ __align__(1024) char smem[];
    const uint32_t sb = smem_u32(smem);
    const int tid = threadIdx.x, lane = tid & 31, w = tid >> 5;
    const int qt = 3 - blockIdx.x;       // long CTAs first
    const int bh = blockIdx.y;
    const int b = bh >> 4, h = bh & 15;
    const int g = lane >> 2, tig = lane & 3;

    const uint32_t QB = sb;              // Q mbarrier
    const uint32_t FB = sb + 8;          // kv full barriers: stage0 @+8, stage1 @+16
    const uint32_t QT = sb + 1024;       // Q hi 16KB | Q lo 16KB
    const uint32_t KV = sb + 1024 + 32768; // 2 stages x (Kh|Kl|Vh|Vl each 8KB)

    if (tid == 0) { MBAR_INIT(QB, 1); MBAR_INIT(FB, 1); MBAR_INIT(FB + 8, 1); }
    __syncthreads();

    const size_t bh_off = (size_t)bh * LL * HDIM;
    const __nv_bfloat16* kh = g_kh + bh_off;
    const __nv_bfloat16* kl = g_kl + bh_off;
    const __nv_bfloat16* vh = g_vh + bh_off;
    const __nv_bfloat16* vl = g_vl + bh_off;

    const int jmax = 2 * qt + 2;

    auto issue = [&](int jt) {
        int s = jt & 1;
        uint32_t fb = FB + s * 8;
        uint32_t st = KV + s * 32768;
        MBAR_EXPECT_TX(fb, 32768);
        bulk_g2s(st,         kh + (size_t)jt * 4096, 8192, fb);
        bulk_g2s(st + 8192,  kl + (size_t)jt * 4096, 8192, fb);
        bulk_g2s(st + 16384, vh + (size_t)jt * 4096, 8192, fb);
        bulk_g2s(st + 24576, vl + (size_t)jt * 4096, 8192, fb);
    };
    if (tid == 0) {
        MBAR_EXPECT_TX(QB, 32768);
        bulk_g2s(QT,         g_qh + bh_off + (size_t)qt * 128 * 64, 16384, QB);
        bulk_g2s(QT + 16384, g_ql + bh_off + (size_t)qt * 128 * 64, 16384, QB);
        issue(0);
        issue(1);
    }

    float o[8][4];
    #pragma unroll
    for (int nf = 0; nf < 8; nf++)
        #pragma unroll
        for (int r = 0; r < 4; r++) o[nf][r] = 0.f;
    float m0 = -1e30f, m1 = -1e30f, l0 = 0.f, l1 = 0.f;

    const int rowmin = qt * 128 + w * 16;

    mbar_wait(QB, 0);

    for (int jt = 0; jt < jmax; jt++) {
        const int s = jt & 1;
        mbar_wait(FB + s * 8, (uint32_t)((jt >> 1) & 1));
        const uint32_t kb = KV + s * 32768;

        if (jt * 64 <= rowmin + 15) {      // not fully masked for this warp
            float p[8][4];
            #pragma unroll
            for (int nf = 0; nf < 8; nf++)
                #pragma unroll
                for (int r = 0; r < 4; r++) p[nf][r] = 0.f;

            // S = Q K^T (3-term split)
            #pragma unroll
            for (int ks = 0; ks < 4; ks++) {
                uint32_t qoff = (uint32_t)(w * 16 + (lane & 15)) * 128
                                + (uint32_t)(lane >> 4) * 16 + (uint32_t)ks * 32;
                uint32_t swq = qoff ^ ((qoff >> 3) & 0x70);
                uint32_t ah[4], al[4];
                ldsm_x4(ah, QT + swq);
                ldsm_x4(al, QT + 16384 + swq);
                #pragma unroll
                for (int nfp = 0; nfp < 4; nfp++) {
                    uint32_t koff = (uint32_t)(nfp * 16 + (lane & 7) + ((lane & 16) >> 1)) * 128
                                    + (uint32_t)ks * 32 + ((lane & 8) << 1);
                    uint32_t swk = koff ^ ((koff >> 3) & 0x70);
                    uint32_t kbh[4], kbl[4];
                    ldsm_x4(kbh, kb + swk);
                    ldsm_x4(kbl, kb + 8192 + swk);
                    mma_bf16(p[2 * nfp],     ah, &kbh[0]);
                    mma_bf16(p[2 * nfp],     ah, &kbl[0]);
                    mma_bf16(p[2 * nfp],     al, &kbh[0]);
                    mma_bf16(p[2 * nfp + 1], ah, &kbh[2]);
                    mma_bf16(p[2 * nfp + 1], ah, &kbl[2]);
                    mma_bf16(p[2 * nfp + 1], al, &kbh[2]);
                }
            }

            // scale + causal mask
            const bool need_mask = (jt * 64 + 63) > rowmin;
            #pragma unroll
            for (int nf = 0; nf < 8; nf++)
                #pragma unroll
                for (int r = 0; r < 4; r++) {
                    float v = p[nf][r] * 0.125f;
                    if (need_mask) {
                        int qr = rowmin + g + ((r & 2) << 2);
                        int kc = jt * 64 + 8 * nf + 2 * tig + (r & 1);
                        if (kc > qr) v = -1e30f;
                    }
                    p[nf][r] = v;
                }

            // online softmax
            float mx0 = m0, mx1 = m1;
            #pragma unroll
            for (int nf = 0; nf < 8; nf++) {
                mx0 = fmaxf(mx0, fmaxf(p[nf][0], p[nf][1]));
                mx1 = fmaxf(mx1, fmaxf(p[nf][2], p[nf][3]));
            }
            mx0 = fmaxf(mx0, __shfl_xor_sync(0xffffffffu, mx0, 1));
            mx0 = fmaxf(mx0, __shfl_xor_sync(0xffffffffu, mx0, 2));
            mx1 = fmaxf(mx1, __shfl_xor_sync(0xffffffffu, mx1, 1));
            mx1 = fmaxf(mx1, __shfl_xor_sync(0xffffffffu, mx1, 2));
            float c0 = __expf(m0 - mx0), c1 = __expf(m1 - mx1);
            m0 = mx0; m1 = mx1;
            float s0 = 0.f, s1 = 0.f;
            #pragma unroll
            for (int nf = 0; nf < 8; nf++) {
                p[nf][0] = __expf(p[nf][0] - mx0); s0 += p[nf][0];
                p[nf][1] = __expf(p[nf][1] - mx0); s0 += p[nf][1];
                p[nf][2] = __expf(p[nf][2] - mx1); s1 += p[nf][2];
                p[nf][3] = __expf(p[nf][3] - mx1); s1 += p[nf][3];
            }
            s0 += __shfl_xor_sync(0xffffffffu, s0, 1);
            s0 += __shfl_xor_sync(0xffffffffu, s0, 2);
            s1 += __shfl_xor_sync(0xffffffffu, s1, 1);
            s1 += __shfl_xor_sync(0xffffffffu, s1, 2);
            l0 = l0 * c0 + s0;
            l1 = l1 * c1 + s1;
            #pragma unroll
            for (int nf = 0; nf < 8; nf++) {
                o[nf][0] *= c0; o[nf][1] *= c0;
                o[nf][2] *= c1; o[nf][3] *= c1;
            }

            // O += P V (3-term split; P C-frags -> A-frags in registers)
            #pragma unroll
            for (int j = 0; j < 4; j++) {
                uint32_t pah[4], pal[4];
                #pragma unroll
                for (int half = 0; half < 2; half++) {
                    const float* pf = p[2 * j + half];
                    __nv_bfloat16 h0 = __float2bfloat16(pf[0]);
                    __nv_bfloat16 h1 = __float2bfloat16(pf[1]);
                    __nv_bfloat16 h2 = __float2bfloat16(pf[2]);
                    __nv_bfloat16 h3 = __float2bfloat16(pf[3]);
                    pah[2 * half]     = pack_bf2(h0, h1);
                    pah[2 * half + 1] = pack_bf2(h2, h3);
                    pal[2 * half]     = pack_bf2(__float2bfloat16(pf[0] - __bfloat162float(h0)),
                                                 __float2bfloat16(pf[1] - __bfloat162float(h1)));
                    pal[2 * half + 1] = pack_bf2(__float2bfloat16(pf[2] - __bfloat162float(h2)),
                                                 __float2bfloat16(pf[3] - __bfloat162float(h3)));
                }
                #pragma unroll
                for (int nfp = 0; nfp < 4; nfp++) {
                    uint32_t voff = (uint32_t)(16 * j + (lane & 7) + (lane & 8)) * 128
                                    + (uint32_t)nfp * 32 + (lane & 16);
                    uint32_t swv = voff ^ ((voff >> 3) & 0x70);
                    uint32_t vbh[4], vbl[4];
                    ldsm_x4t(vbh, kb + 16384 + swv);
                    ldsm_x4t(vbl, kb + 24576 + swv);
                    mma_bf16(o[2 * nfp],     pah, &vbh[0]);
                    mma_bf16(o[2 * nfp],     pah, &vbl[0]);
                    mma_bf16(o[2 * nfp],     pal, &vbh[0]);
                    mma_bf16(o[2 * nfp + 1], pah, &vbh[2]);
                    mma_bf16(o[2 * nfp + 1], pah, &vbl[2]);
                    mma_bf16(o[2 * nfp + 1], pal, &vbh[2]);
                }
            }
        }
        __syncthreads();
        if (tid == 0 && jt + 2 < jmax) issue(jt + 2);
    }

    // epilogue: O /= l; write AO as hi/lo swizzled tile (rt = b*4+qt, kc = h)
    const float i0 = 1.f / l0, i1 = 1.f / l1;
    const size_t tb = (((size_t)(b * 4 + qt) * 16) + h) * 16384;   // bytes
    char* dh = (char*)g_xh + tb;
    char* dl = (char*)g_xl + tb;
    #pragma unroll
    for (int nf = 0; nf < 8; nf++) {
        #pragma unroll
        for (int rh = 0; rh < 2; rh++) {
            float y0 = o[nf][2 * rh]     * (rh ? i1 : i0);
            float y1 = o[nf][2 * rh + 1] * (rh ? i1 : i0);
            __nv_bfloat16 hb0 = __float2bfloat16(y0);
            __nv_bfloat16 hb1 = __float2bfloat16(y1);
            __nv_bfloat16 lb0 = __float2bfloat16(y0 - __bfloat162float(hb0));
            __nv_bfloat16 lb1 = __float2bfloat16(y1 - __bfloat162float(hb1));
            uint32_t off = (uint32_t)((w * 16 + g + 8 * rh) * 128 + (8 * nf + 2 * tig) * 2);
            uint32_t sw = off ^ ((off >> 3) & 0x70);
            *(uint32_t*)(dh + sw) = pack_bf2(hb0, hb1);
            *(uint32_t*)(dl + sw) = pack_bf2(lb0, lb1);
        }
    }
}

// ---------------- launch ----------------
extern "C" void kernel_launch(void* const* d_in, const int* in_sizes, int n_in,
                              void* d_out, int out_size) {
    const float* x  = (const float*)d_in[0];
    const float* qw = (const float*)d_in[1];
    const float* kw = (const float*)d_in[2];
    const float* vw = (const float*)d_in[3];
    const float* ow = (const float*)d_in[4];
    const float* rw = (const float*)d_in[5];
    const float* rb = (const float*)d_in[6];
    float* out = (float*)d_out;

    const int GEMM_SMEM = 1024 + 3 * 65536;
    cudaFuncSetAttribute(hmma_gemm_kernel<0>, cudaFuncAttributeMaxDynamicSharedMemorySize, GEMM_SMEM);
    cudaFuncSetAttribute(hmma_gemm_kernel<1>, cudaFuncAttributeMaxDynamicSharedMemorySize, GEMM_SMEM);
    cudaFuncSetAttribute(hmma_gemm_kernel<2>, cudaFuncAttributeMaxDynamicSharedMemorySize, GEMM_SMEM);
    cudaFuncSetAttribute(hmma_gemm_kernel<3>, cudaFuncAttributeMaxDynamicSharedMemorySize, GEMM_SMEM);
    const int ATTN_SMEM = 1024 + 32768 + 2 * 32768;   // 99328
    cudaFuncSetAttribute(attn_kernel, cudaFuncAttributeMaxDynamicSharedMemorySize, ATTN_SMEM);

    rope_init_kernel<<<(LL * 32 + 255) / 256, 256>>>();

    int write_probs = (out_size >= BB * LL * DD + BB * EE) ? 1 : 0;
    router_kernel<<<BB, 256>>>(x, rw, rb, out + (size_t)BB * LL * DD, write_probs);

    convert_x_kernel<<<dim3(16, 128), 256>>>(x);
    convert_w_kernel<<<dim3(16, 8, 8), 256>>>(qw, 0);
    convert_w_kernel<<<dim3(16, 8, 8), 256>>>(kw, 1);
    convert_w_kernel<<<dim3(16, 8, 8), 256>>>(vw, 2);
    convert_w_kernel<<<dim3(16, 8, 8), 256>>>(ow, 3);

    dim3 g(DD / 128, LL / 128, BB);   // (8, 4, 32)
    hmma_gemm_kernel<0><<<g, 256, GEMM_SMEM>>>(nullptr);
    hmma_gemm_kernel<1><<<g, 256, GEMM_SMEM>>>(nullptr);
    hmma_gemm_kernel<2><<<g, 256, GEMM_SMEM>>>(nullptr);

    attn_kernel<<<dim3(4, BB * HH), 256, ATTN_SMEM>>>();

    hmma_gemm_kernel<3><<<g, 256, GEMM_SMEM>>>(out);
}

// round 5
// speedup vs baseline: 3.2647x; 1.0076x over previous
#include <cuda_runtime.h>
#include <cuda_bf16.h>
#include <cstdint>
#include <math.h>

#define BB 32
#define LL 512
#define DD 1024
#define HH 16
#define HDIM 64
#define EE 8

// ---------------- scratch (device globals; no allocation allowed) ----------------
__device__ float g_cos[LL * 32];
__device__ float g_sin[LL * 32];
__device__ int   g_routes[BB];

// X/AO tiles: [rt(128)][kc(16)] each 128 rows x 64 cols bf16 (16KB), SW128-swizzled
__device__ __nv_bfloat16 g_xh[(size_t)16384 * 1024];
__device__ __nv_bfloat16 g_xl[(size_t)16384 * 1024];
// W^T tiles: [wsel(4)][e(8)][nt(8)][kc(16)] each 128(n) x 64(k) bf16, SW128-swizzled
__device__ __nv_bfloat16 g_wth[(size_t)4 * 8 * 1024 * 1024];
__device__ __nv_bfloat16 g_wtl[(size_t)4 * 8 * 1024 * 1024];
// q/k/v bf16 hi/lo: [B*H][512][64], SW128-swizzled 128B rows
__device__ __nv_bfloat16 g_qh[(size_t)BB * HH * LL * HDIM];
__device__ __nv_bfloat16 g_ql[(size_t)BB * HH * LL * HDIM];
__device__ __nv_bfloat16 g_kh[(size_t)BB * HH * LL * HDIM];
__device__ __nv_bfloat16 g_kl[(size_t)BB * HH * LL * HDIM];
__device__ __nv_bfloat16 g_vh[(size_t)BB * HH * LL * HDIM];
__device__ __nv_bfloat16 g_vl[(size_t)BB * HH * LL * HDIM];

// ---------------- PTX helpers ----------------
__device__ __forceinline__ uint32_t smem_u32(const void* p) {
    uint32_t a;
    asm("{ .reg .u64 t; cvta.to.shared.u64 t, %1; cvt.u32.u64 %0, t; }" : "=r"(a) : "l"(p));
    return a;
}

#define MBAR_INIT(a, n) \
    asm volatile("mbarrier.init.shared.b64 [%0], %1;" :: "r"(a), "r"((uint32_t)(n)) : "memory")
#define MBAR_EXPECT_TX(a, b) \
    asm volatile("mbarrier.arrive.expect_tx.shared.b64 _, [%0], %1;" :: "r"(a), "r"((uint32_t)(b)) : "memory")

__device__ __forceinline__ void mbar_wait(uint32_t mbar, uint32_t parity) {
    asm volatile(
        "{\n\t.reg .pred P;\n\t"
        "WL_%=:\n\t"
        "mbarrier.try_wait.parity.acquire.cta.shared::cta.b64 P, [%0], %1, 0x989680;\n\t"
        "@P bra.uni WD_%=;\n\t"
        "bra.uni WL_%=;\n\t"
        "WD_%=:\n\t}"
        :: "r"(mbar), "r"(parity) : "memory");
}

__device__ __forceinline__ void bulk_g2s(uint32_t dst, const void* src, uint32_t bytes, uint32_t mbar) {
    asm volatile(
        "cp.async.bulk.shared::cluster.global.mbarrier::complete_tx::bytes [%0], [%1], %2, [%3];"
        :: "r"(dst), "l"(src), "r"(bytes), "r"(mbar) : "memory");
}

__device__ __forceinline__ void ldsm_x4(uint32_t* r, uint32_t a) {
    asm volatile("ldmatrix.sync.aligned.m8n8.x4.shared.b16 {%0,%1,%2,%3}, [%4];"
                 : "=r"(r[0]), "=r"(r[1]), "=r"(r[2]), "=r"(r[3]) : "r"(a));
}
__device__ __forceinline__ void ldsm_x4t(uint32_t* r, uint32_t a) {
    asm volatile("ldmatrix.sync.aligned.m8n8.x4.trans.shared.b16 {%0,%1,%2,%3}, [%4];"
                 : "=r"(r[0]), "=r"(r[1]), "=r"(r[2]), "=r"(r[3]) : "r"(a));
}
__device__ __forceinline__ void mma_bf16(float* d, const uint32_t* a, const uint32_t* b) {
    asm volatile(
        "mma.sync.aligned.m16n8k16.row.col.f32.bf16.bf16.f32 "
        "{%0,%1,%2,%3}, {%4,%5,%6,%7}, {%8,%9}, {%0,%1,%2,%3};"
        : "+f"(d[0]), "+f"(d[1]), "+f"(d[2]), "+f"(d[3])
        : "r"(a[0]), "r"(a[1]), "r"(a[2]), "r"(a[3]), "r"(b[0]), "r"(b[1]));
}

__device__ __forceinline__ uint32_t pack_bf2(__nv_bfloat16 a, __nv_bfloat16 b) {
    return (uint32_t)__bfloat16_as_ushort(a) | ((uint32_t)__bfloat16_as_ushort(b) << 16);
}

// ---------------- RoPE tables ----------------
__global__ void rope_init_kernel() {
    int idx = blockIdx.x * blockDim.x + threadIdx.x;
    if (idx >= LL * 32) return;
    int l = idx >> 5;
    int jp = idx & 31;
    float inv = 1.0f / powf(10000.0f, (float)(2 * jp) / 64.0f);
    float ang = (float)l * inv;
    g_cos[idx] = cosf(ang);
    g_sin[idx] = sinf(ang);
}

// ---------------- router ----------------
__global__ void router_kernel(const float* __restrict__ x,
                              const float* __restrict__ rw,
                              const float* __restrict__ rb,
                              float* __restrict__ probs_out,
                              int write_probs) {
    int b = blockIdx.x;
    __shared__ float mean[DD];
    __shared__ float logits[EE];

    for (int d = threadIdx.x; d < DD; d += blockDim.x) {
        const float* xp = x + (size_t)b * LL * DD + d;
        float s = 0.f;
        #pragma unroll 8
        for (int l = 0; l < LL; l++) s += xp[(size_t)l * DD];
        mean[d] = s * (1.0f / (float)LL);
    }
    __syncthreads();

    int w = threadIdx.x >> 5;
    int lane = threadIdx.x & 31;
    if (w < EE) {
        float s = 0.f;
        for (int d = lane; d < DD; d += 32) s += mean[d] * rw[d * EE + w];
        #pragma unroll
        for (int o = 16; o > 0; o >>= 1) s += __shfl_down_sync(0xffffffffu, s, o);
        if (lane == 0) logits[w] = s + rb[w];
    }
    __syncthreads();

    if (threadIdx.x == 0) {
        float m = logits[0]; int arg = 0;
        #pragma unroll
        for (int e = 1; e < EE; e++) if (logits[e] > m) { m = logits[e]; arg = e; }
        float p[EE], sum = 0.f;
        #pragma unroll
        for (int e = 0; e < EE; e++) { p[e] = expf(logits[e] - m); sum += p[e]; }
        if (write_probs) {
            float inv = 1.0f / sum;
            #pragma unroll
            for (int e = 0; e < EE; e++) probs_out[b * EE + e] = p[e] * inv;
        }
        g_routes[b] = arg;
    }
}

// ---------------- convert X -> tiled swizzled bf16 hi/lo ----------------
__global__ void convert_x_kernel(const float* __restrict__ src) {
    const int kc = blockIdx.x, rt = blockIdx.y;
    const int t = threadIdx.x;
    const size_t tile_elem = ((size_t)rt * 16 + kc) * 8192;
    char* dh = (char*)(g_xh + tile_elem);
    char* dl = (char*)(g_xl + tile_elem);

    #pragma unroll
    for (int i = 0; i < 4; i++) {
        int u = t + i * 256;             // 0..1023 16B units
        int r = u >> 3, k8 = u & 7;
        const float* p = src + ((size_t)(rt * 128 + r)) * DD + kc * 64 + k8 * 8;
        float4 a = *(const float4*)p;
        float4 b4 = *(const float4*)(p + 4);
        float xs[8] = {a.x, a.y, a.z, a.w, b4.x, b4.y, b4.z, b4.w};
        __nv_bfloat16 hi[8], lo[8];
        #pragma unroll
        for (int j = 0; j < 8; j++) {
            hi[j] = __float2bfloat16(xs[j]);
            lo[j] = __float2bfloat16(xs[j] - __bfloat162float(hi[j]));
        }
        uint32_t off = (uint32_t)(u * 16);
        off ^= (off >> 3) & 0x70;        // SW128
        uint4 hv = make_uint4(pack_bf2(hi[0], hi[1]), pack_bf2(hi[2], hi[3]),
                              pack_bf2(hi[4], hi[5]), pack_bf2(hi[6], hi[7]));
        uint4 lv = make_uint4(pack_bf2(lo[0], lo[1]), pack_bf2(lo[2], lo[3]),
                              pack_bf2(lo[4], lo[5]), pack_bf2(lo[6], lo[7]));
        *(uint4*)(dh + off) = hv;
        *(uint4*)(dl + off) = lv;
    }
}

// ---------------- convert+transpose W -> tiled swizzled bf16 hi/lo ----------------
__global__ void convert_w_kernel(const float* __restrict__ W, int wsel) {
    __shared__ float sm[64][129];
    const int kc = blockIdx.x, nt = blockIdx.y, e = blockIdx.z;
    const int t = threadIdx.x;
    const float* src = W + ((size_t)e * DD + kc * 64) * DD + nt * 128;

    #pragma unroll
    for (int i = 0; i < 8; i++) {
        int idx = t + i * 256;           // 0..2047 float4s
        int kr = idx >> 5, nc = (idx & 31) << 2;
        float4 v = *(const float4*)(src + (size_t)kr * DD + nc);
        sm[kr][nc] = v.x; sm[kr][nc + 1] = v.y; sm[kr][nc + 2] = v.z; sm[kr][nc + 3] = v.w;
    }
    __syncthreads();

    const size_t tile_elem = (((size_t)e * 8 + nt) * 16 + kc) * 8192;
    char* dh = (char*)(g_wth + (size_t)wsel * 8388608 + tile_elem);
    char* dl = (char*)(g_wtl + (size_t)wsel * 8388608 + tile_elem);

    #pragma unroll
    for (int i = 0; i < 4; i++) {
        int u = t + i * 256;             // 0..1023
        int n = u >> 3, k8 = u & 7;
        __nv_bfloat16 hi[8], lo[8];
        #pragma unroll
        for (int j = 0; j < 8; j++) {
            float x = sm[k8 * 8 + j][n];
            hi[j] = __float2bfloat16(x);
            lo[j] = __float2bfloat16(x - __bfloat162float(hi[j]));
        }
        uint32_t off = (uint32_t)(u * 16);
        off ^= (off >> 3) & 0x70;
        uint4 hv = make_uint4(pack_bf2(hi[0], hi[1]), pack_bf2(hi[2], hi[3]),
                              pack_bf2(hi[4], hi[5]), pack_bf2(hi[6], hi[7]));
        uint4 lv = make_uint4(pack_bf2(lo[0], lo[1]), pack_bf2(lo[2], lo[3]),
                              pack_bf2(lo[4], lo[5]), pack_bf2(lo[6], lo[7]));
        *(uint4*)(dh + off) = hv;
        *(uint4*)(dl + off) = lv;
    }
}

// ---------------- HMMA GEMM: CTA tile 128x256, warp tile 64x64 (2m x 4n warps) -------
// K=1024 in 16 chunks of 64; 2-stage bulk-copy pipeline (96KB/stage).
// mode 0: q (RoPE, bf16 hi/lo out), 1: k (RoPE, hi/lo), 2: v (hi/lo), 3: out proj (fp32)
// Launch: grid.x = 4*modes, mode = mode0 + (blockIdx.x>>2), nt = blockIdx.x&3.
__global__ void __launch_bounds__(256, 1) hmma_gemm_kernel(float* __restrict__ out, int mode0) {
    extern __shared__ __align__(1024) char smem[];
    const uint32_t sb = smem_u32(smem);
    const int tid = threadIdx.x;
    const int lane = tid & 31, wid = tid >> 5;
    const int wm = wid >> 2, wn = wid & 3;            // 2(m) x 4(n)
    const int nt = blockIdx.x & 3;
    const int mode = mode0 + (blockIdx.x >> 2);
    const int mt = blockIdx.y, b = blockIdx.z;
    const int e = g_routes[b];

    const uint32_t FULLB = sb;                  // 2 mbarriers
    const uint32_t TILES = sb + 1024;           // 2 stages x 96KB
    // stage layout: Ah 0 | Al 16K | Bh0 32K | Bh1 48K | Bl0 64K | Bl1 80K

    if (tid == 0) { MBAR_INIT(FULLB, 1); MBAR_INIT(FULLB + 8, 1); }
    __syncthreads();

    const size_t a_t0 = ((size_t)(b * 4 + mt) * 16) * 8192;
    const __nv_bfloat16* Ah = g_xh + a_t0;
    const __nv_bfloat16* Al = g_xl + a_t0;
    const size_t wb = (size_t)mode * 8388608;
    const size_t b_t0 = (((size_t)e * 8) + 2 * nt) * 16 * 8192;     // tile (2nt, kc=0)
    const __nv_bfloat16* Bh0 = g_wth + wb + b_t0;
    const __nv_bfloat16* Bh1 = Bh0 + (size_t)16 * 8192;             // tile (2nt+1)
    const __nv_bfloat16* Bl0 = g_wtl + wb + b_t0;
    const __nv_bfloat16* Bl1 = Bl0 + (size_t)16 * 8192;

    auto issue = [&](int c) {
        int s = c & 1;
        uint32_t fb = FULLB + s * 8;
        uint32_t st = TILES + s * 98304;
        MBAR_EXPECT_TX(fb, 98304);
        bulk_g2s(st,         Ah  + (size_t)c * 8192, 16384, fb);
        bulk_g2s(st + 16384, Al  + (size_t)c * 8192, 16384, fb);
        bulk_g2s(st + 32768, Bh0 + (size_t)c * 8192, 16384, fb);
        bulk_g2s(st + 49152, Bh1 + (size_t)c * 8192, 16384, fb);
        bulk_g2s(st + 65536, Bl0 + (size_t)c * 8192, 16384, fb);
        bulk_g2s(st + 81920, Bl1 + (size_t)c * 8192, 16384, fb);
    };
    if (tid == 0) { issue(0); issue(1); }

    float acc[4][8][4];
    #pragma unroll
    for (int mf = 0; mf < 4; mf++)
        #pragma unroll
        for (int nf = 0; nf < 8; nf++)
            #pragma unroll
            for (int r = 0; r < 4; r++) acc[mf][nf][r] = 0.f;

    // A ldmatrix address components (per-warp 64 m-rows)
    const uint32_t a_row  = (uint32_t)(wm * 64 + (lane & 15)) * 128;
    const uint32_t a_koff = (uint32_t)(lane >> 4) * 16;
    // B: warp wn covers n 64wn..64wn+63; tile half = wn>>1, row base (wn&1)*64
    const uint32_t b_tile = 32768 + (uint32_t)(wn >> 1) * 16384;
    const uint32_t b_row  = (uint32_t)((wn & 1) * 64 + (lane & 7) + ((lane >> 4) << 3)) * 128;
    const uint32_t b_koff = (uint32_t)((lane >> 3) & 1) * 16;

    for (int c = 0; c < 16; c++) {
        const int s = c & 1;
        mbar_wait(FULLB + s * 8, (uint32_t)((c >> 1) & 1));
        const uint32_t base = TILES + s * 98304;

        #pragma unroll
        for (int ks = 0; ks < 4; ks++) {
            const uint32_t k0b = (uint32_t)ks * 32;
            uint32_t ah[4][4], al[4][4];
            #pragma unroll
            for (int mf = 0; mf < 4; mf++) {
                uint32_t byt = a_row + (uint32_t)mf * 2048 + a_koff + k0b;
                uint32_t sw = byt ^ ((byt >> 3) & 0x70);
                ldsm_x4(ah[mf], base + sw);
                ldsm_x4(al[mf], base + 16384 + sw);
            }
            #pragma unroll
            for (int p = 0; p < 4; p++) {       // 16 n-cols per iteration
                uint32_t byt = b_row + (uint32_t)p * 2048 + b_koff + k0b;
                uint32_t sw = byt ^ ((byt >> 3) & 0x70);
                uint32_t bh[4], bl[4];
                ldsm_x4(bh, base + b_tile + sw);
                ldsm_x4(bl, base + b_tile + 32768 + sw);
                #pragma unroll
                for (int mf = 0; mf < 4; mf++) {
                    mma_bf16(acc[mf][2 * p],     ah[mf], &bh[0]);
                    mma_bf16(acc[mf][2 * p],     ah[mf], &bl[0]);
                    mma_bf16(acc[mf][2 * p],     al[mf], &bh[0]);
                    mma_bf16(acc[mf][2 * p + 1], ah[mf], &bh[2]);
                    mma_bf16(acc[mf][2 * p + 1], ah[mf], &bl[2]);
                    mma_bf16(acc[mf][2 * p + 1], al[mf], &bh[2]);
                }
            }
        }
        __syncthreads();
        if (tid == 0 && c + 2 < 16) issue(c + 2);
    }

    // ---------------- epilogue ----------------
    const int l_base = mt * 128 + wm * 64 + (lane >> 2);
    const int tig = lane & 3;
    const int hglob = nt * 4 + wn;               // whole warp same 64-col group

    #pragma unroll
    for (int mf = 0; mf < 4; mf++) {
        #pragma unroll
        for (int rh = 0; rh < 2; rh++) {
            const int l = l_base + mf * 16 + 8 * rh;
            #pragma unroll
            for (int nf = 0; nf < 8; nf++) {
                const int d = 8 * nf + 2 * tig;
                float x0 = acc[mf][nf][2 * rh];
                float x1 = acc[mf][nf][2 * rh + 1];
                if (mode == 3) {
                    float2* dst = (float2*)(out + ((size_t)b * LL + l) * DD + hglob * 64 + d);
                    *dst = make_float2(x0, x1);
                } else {
                    float y0, y1;
                    if (mode == 2) { y0 = x0; y1 = x1; }
                    else {
                        const int p = d >> 1;
                        float cs = g_cos[l * 32 + p];
                        float sn = g_sin[l * 32 + p];
                        y0 = x0 * cs - x1 * sn;
                        y1 = x1 * cs + x0 * sn;
                    }
                    __nv_bfloat16 hb0 = __float2bfloat16(y0);
                    __nv_bfloat16 hb1 = __float2bfloat16(y1);
                    __nv_bfloat16 lb0 = __float2bfloat16(y0 - __bfloat162float(hb0));
                    __nv_bfloat16 lb1 = __float2bfloat16(y1 - __bfloat162float(hb1));
                    uint32_t off = (uint32_t)((((b * HH + hglob) * LL) + l) * 128 + d * 2);
                    uint32_t sw = off ^ ((off >> 3) & 0x70);
                    char* bhp = (char*)((mode == 0) ? g_qh : (mode == 1) ? g_kh : g_vh);
                    char* blp = (char*)((mode == 0) ? g_ql : (mode == 1) ? g_kl : g_vl);
                    *(uint32_t*)(bhp + sw) = pack_bf2(hb0, hb1);
                    *(uint32_t*)(blp + sw) = pack_bf2(lb0, lb1);
                }
            }
        }
    }
}

// ---------------- flash attention on HMMA: 128 q-rows/CTA, 8 warps x 16 rows ---------
__global__ void __launch_bounds__(256, 2) attn_kernel() {
    extern __shared__ __align__(1024) char smem[];
    const uint32_t sb = smem_u32(smem);
    const int tid = threadIdx.x, lane = tid & 31, w = tid >> 5;
    const int qt = 3 - blockIdx.x;       // long CTAs first
    const int bh = blockIdx.y;
    const int b = bh >> 4, h = bh & 15;
    const int g = lane >> 2, tig = lane & 3;

    const uint32_t QB = sb;              // Q mbarrier
    const uint32_t FB = sb + 8;          // kv full barriers: stage0 @+8, stage1 @+16
    const uint32_t QT = sb + 1024;       // Q hi 16KB | Q lo 16KB
    const uint32_t KV = sb + 1024 + 32768; // 2 stages x (Kh|Kl|Vh|Vl each 8KB)

    if (tid == 0) { MBAR_INIT(QB, 1); MBAR_INIT(FB, 1); MBAR_INIT(FB + 8, 1); }
    __syncthreads();

    const size_t bh_off = (size_t)bh * LL * HDIM;
    const __nv_bfloat16* kh = g_kh + bh_off;
    const __nv_bfloat16* kl = g_kl + bh_off;
    const __nv_bfloat16* vh = g_vh + bh_off;
    const __nv_bfloat16* vl = g_vl + bh_off;

    const int jmax = 2 * qt + 2;

    auto issue = [&](int jt) {
        int s = jt & 1;
        uint32_t fb = FB + s * 8;
        uint32_t st = KV + s * 32768;
        MBAR_EXPECT_TX(fb, 32768);
        bulk_g2s(st,         kh + (size_t)jt * 4096, 8192, fb);
        bulk_g2s(st + 8192,  kl + (size_t)jt * 4096, 8192, fb);
        bulk_g2s(st + 16384, vh + (size_t)jt * 4096, 8192, fb);
        bulk_g2s(st + 24576, vl + (size_t)jt * 4096, 8192, fb);
    };
    if (tid == 0) {
        MBAR_EXPECT_TX(QB, 32768);
        bulk_g2s(QT,         g_qh + bh_off + (size_t)qt * 128 * 64, 16384, QB);
        bulk_g2s(QT + 16384, g_ql + bh_off + (size_t)qt * 128 * 64, 16384, QB);
        issue(0);
        issue(1);
    }

    float o[8][4];
    #pragma unroll
    for (int nf = 0; nf < 8; nf++)
        #pragma unroll
        for (int r = 0; r < 4; r++) o[nf][r] = 0.f;
    float m0 = -1e30f, m1 = -1e30f, l0 = 0.f, l1 = 0.f;

    const int rowmin = qt * 128 + w * 16;

    mbar_wait(QB, 0);

    for (int jt = 0; jt < jmax; jt++) {
        const int s = jt & 1;
        mbar_wait(FB + s * 8, (uint32_t)((jt >> 1) & 1));
        const uint32_t kb = KV + s * 32768;

        if (jt * 64 <= rowmin + 15) {      // not fully masked for this warp
            float p[8][4];
            #pragma unroll
            for (int nf = 0; nf < 8; nf++)
                #pragma unroll
                for (int r = 0; r < 4; r++) p[nf][r] = 0.f;

            // S = Q K^T (3-term split)
            #pragma unroll
            for (int ks = 0; ks < 4; ks++) {
                uint32_t qoff = (uint32_t)(w * 16 + (lane & 15)) * 128
                                + (uint32_t)(lane >> 4) * 16 + (uint32_t)ks * 32;
                uint32_t swq = qoff ^ ((qoff >> 3) & 0x70);
                uint32_t ah[4], al[4];
                ldsm_x4(ah, QT + swq);
                ldsm_x4(al, QT + 16384 + swq);
                #pragma unroll
                for (int nfp = 0; nfp < 4; nfp++) {
                    uint32_t koff = (uint32_t)(nfp * 16 + (lane & 7) + ((lane & 16) >> 1)) * 128
                                    + (uint32_t)ks * 32 + ((lane & 8) << 1);
                    uint32_t swk = koff ^ ((koff >> 3) & 0x70);
                    uint32_t kbh[4], kbl[4];
                    ldsm_x4(kbh, kb + swk);
                    ldsm_x4(kbl, kb + 8192 + swk);
                    mma_bf16(p[2 * nfp],     ah, &kbh[0]);
                    mma_bf16(p[2 * nfp],     ah, &kbl[0]);
                    mma_bf16(p[2 * nfp],     al, &kbh[0]);
                    mma_bf16(p[2 * nfp + 1], ah, &kbh[2]);
                    mma_bf16(p[2 * nfp + 1], ah, &kbl[2]);
                    mma_bf16(p[2 * nfp + 1], al, &kbh[2]);
                }
            }

            // scale + causal mask
            const bool need_mask = (jt * 64 + 63) > rowmin;
            #pragma unroll
            for (int nf = 0; nf < 8; nf++)
                #pragma unroll
                for (int r = 0; r < 4; r++) {
                    float v = p[nf][r] * 0.125f;
                    if (need_mask) {
                        int qr = rowmin + g + ((r & 2) << 2);
                        int kc = jt * 64 + 8 * nf + 2 * tig + (r & 1);
                        if (kc > qr) v = -1e30f;
                    }
                    p[nf][r] = v;
                }

            // online softmax
            float mx0 = m0, mx1 = m1;
            #pragma unroll
            for (int nf = 0; nf < 8; nf++) {
                mx0 = fmaxf(mx0, fmaxf(p[nf][0], p[nf][1]));
                mx1 = fmaxf(mx1, fmaxf(p[nf][2], p[nf][3]));
            }
            mx0 = fmaxf(mx0, __shfl_xor_sync(0xffffffffu, mx0, 1));
            mx0 = fmaxf(mx0, __shfl_xor_sync(0xffffffffu, mx0, 2));
            mx1 = fmaxf(mx1, __shfl_xor_sync(0xffffffffu, mx1, 1));
            mx1 = fmaxf(mx1, __shfl_xor_sync(0xffffffffu, mx1, 2));
            float c0 = __expf(m0 - mx0), c1 = __expf(m1 - mx1);
            m0 = mx0; m1 = mx1;
            float s0 = 0.f, s1 = 0.f;
            #pragma unroll
            for (int nf = 0; nf < 8; nf++) {
                p[nf][0] = __expf(p[nf][0] - mx0); s0 += p[nf][0];
                p[nf][1] = __expf(p[nf][1] - mx0); s0 += p[nf][1];
                p[nf][2] = __expf(p[nf][2] - mx1); s1 += p[nf][2];
                p[nf][3] = __expf(p[nf][3] - mx1); s1 += p[nf][3];
            }
            s0 += __shfl_xor_sync(0xffffffffu, s0, 1);
            s0 += __shfl_xor_sync(0xffffffffu, s0, 2);
            s1 += __shfl_xor_sync(0xffffffffu, s1, 1);
            s1 += __shfl_xor_sync(0xffffffffu, s1, 2);
            l0 = l0 * c0 + s0;
            l1 = l1 * c1 + s1;
            #pragma unroll
            for (int nf = 0; nf < 8; nf++) {
                o[nf][0] *= c0; o[nf][1] *= c0;
                o[nf][2] *= c1; o[nf][3] *= c1;
            }

            // O += P V (3-term split; P C-frags -> A-frags in registers)
            #pragma unroll
            for (int j = 0; j < 4; j++) {
                uint32_t pah[4], pal[4];
                #pragma unroll
                for (int half = 0; half < 2; half++) {
                    const float* pf = p[2 * j + half];
                    __nv_bfloat16 h0 = __float2bfloat16(pf[0]);
                    __nv_bfloat16 h1 = __float2bfloat16(pf[1]);
                    __nv_bfloat16 h2 = __float2bfloat16(pf[2]);
                    __nv_bfloat16 h3 = __float2bfloat16(pf[3]);
                    pah[2 * half]     = pack_bf2(h0, h1);
                    pah[2 * half + 1] = pack_bf2(h2, h3);
                    pal[2 * half]     = pack_bf2(__float2bfloat16(pf[0] - __bfloat162float(h0)),
                                                 __float2bfloat16(pf[1] - __bfloat162float(h1)));
                    pal[2 * half + 1] = pack_bf2(__float2bfloat16(pf[2] - __bfloat162float(h2)),
                                                 __float2bfloat16(pf[3] - __bfloat162float(h3)));
                }
                #pragma unroll
                for (int nfp = 0; nfp < 4; nfp++) {
                    uint32_t voff = (uint32_t)(16 * j + (lane & 7) + (lane & 8)) * 128
                                    + (uint32_t)nfp * 32 + (lane & 16);
                    uint32_t swv = voff ^ ((voff >> 3) & 0x70);
                    uint32_t vbh[4], vbl[4];
                    ldsm_x4t(vbh, kb + 16384 + swv);
                    ldsm_x4t(vbl, kb + 24576 + swv);
                    mma_bf16(o[2 * nfp],     pah, &vbh[0]);
                    mma_bf16(o[2 * nfp],     pah, &vbl[0]);
                    mma_bf16(o[2 * nfp],     pal, &vbh[0]);
                    mma_bf16(o[2 * nfp + 1], pah, &vbh[2]);
                    mma_bf16(o[2 * nfp + 1], pah, &vbl[2]);
                    mma_bf16(o[2 * nfp + 1], pal, &vbh[2]);
                }
            }
        }
        __syncthreads();
        if (tid == 0 && jt + 2 < jmax) issue(jt + 2);
    }

    // epilogue: O /= l; write AO as hi/lo swizzled tile (rt = b*4+qt, kc = h)
    const float i0 = 1.f / l0, i1 = 1.f / l1;
    const size_t tb = (((size_t)(b * 4 + qt) * 16) + h) * 16384;   // bytes
    char* dh = (char*)g_xh + tb;
    char* dl = (char*)g_xl + tb;
    #pragma unroll
    for (int nf = 0; nf < 8; nf++) {
        #pragma unroll
        for (int rh = 0; rh < 2; rh++) {
            float y0 = o[nf][2 * rh]     * (rh ? i1 : i0);
            float y1 = o[nf][2 * rh + 1] * (rh ? i1 : i0);
            __nv_bfloat16 hb0 = __float2bfloat16(y0);
            __nv_bfloat16 hb1 = __float2bfloat16(y1);
            __nv_bfloat16 lb0 = __float2bfloat16(y0 - __bfloat162float(hb0));
            __nv_bfloat16 lb1 = __float2bfloat16(y1 - __bfloat162float(hb1));
            uint32_t off = (uint32_t)((w * 16 + g + 8 * rh) * 128 + (8 * nf + 2 * tig) * 2);
            uint32_t sw = off ^ ((off >> 3) & 0x70);
            *(uint32_t*)(dh + sw) = pack_bf2(hb0, hb1);
            *(uint32_t*)(dl + sw) = pack_bf2(lb0, lb1);
        }
    }
}

// ---------------- launch ----------------
extern "C" void kernel_launch(void* const* d_in, const int* in_sizes, int n_in,
                              void* d_out, int out_size) {
    const float* x  = (const float*)d_in[0];
    const float* qw = (const float*)d_in[1];
    const float* kw = (const float*)d_in[2];
    const float* vw = (const float*)d_in[3];
    const float* ow = (const float*)d_in[4];
    const float* rw = (const float*)d_in[5];
    const float* rb = (const float*)d_in[6];
    float* out = (float*)d_out;

    const int GEMM_SMEM = 1024 + 2 * 98304;   // 197632
    cudaFuncSetAttribute(hmma_gemm_kernel, cudaFuncAttributeMaxDynamicSharedMemorySize, GEMM_SMEM);
    const int ATTN_SMEM = 1024 + 32768 + 2 * 32768;   // 99328
    cudaFuncSetAttribute(attn_kernel, cudaFuncAttributeMaxDynamicSharedMemorySize, ATTN_SMEM);

    rope_init_kernel<<<(LL * 32 + 255) / 256, 256>>>();

    int write_probs = (out_size >= BB * LL * DD + BB * EE) ? 1 : 0;
    router_kernel<<<BB, 256>>>(x, rw, rb, out + (size_t)BB * LL * DD, write_probs);

    convert_x_kernel<<<dim3(16, 128), 256>>>(x);
    convert_w_kernel<<<dim3(16, 8, 8), 256>>>(qw, 0);
    convert_w_kernel<<<dim3(16, 8, 8), 256>>>(kw, 1);
    convert_w_kernel<<<dim3(16, 8, 8), 256>>>(vw, 2);
    convert_w_kernel<<<dim3(16, 8, 8), 256>>>(ow, 3);

    // fused Q/K/V projection: grid.x = 4 nt * 3 modes
    hmma_gemm_kernel<<<dim3(12, 4, BB), 256, GEMM_SMEM>>>(nullptr, 0);

    attn_kernel<<<dim3(4, BB * HH), 256, ATTN_SMEM>>>();

    // out projection
    hmma_gemm_kernel<<<dim3(4, 4, BB), 256, GEMM_SMEM>>>(out, 3);
}

// round 6
// speedup vs baseline: 3.2766x; 1.0036x over previous
#include <cuda_runtime.h>
#include <cuda_bf16.h>
#include <cstdint>
#include <math.h>

#define BB 32
#define LL 512
#define DD 1024
#define HH 16
#define HDIM 64
#define EE 8

// ---------------- scratch (device globals; no allocation allowed) ----------------
__device__ float g_cos[LL * 32];
__device__ float g_sin[LL * 32];
__device__ int   g_routes[BB];

// X/AO tiles: [rt(128)][kc(16)] each 128 rows x 64 cols bf16 (16KB), SW128-swizzled
__device__ __nv_bfloat16 g_xh[(size_t)16384 * 1024];
__device__ __nv_bfloat16 g_xl[(size_t)16384 * 1024];
// W^T tiles: [wsel(4)][e(8)][nt(8)][kc(16)] each 128(n) x 64(k) bf16, SW128-swizzled
__device__ __nv_bfloat16 g_wth[(size_t)4 * 8 * 1024 * 1024];
__device__ __nv_bfloat16 g_wtl[(size_t)4 * 8 * 1024 * 1024];
// q/k/v bf16 hi/lo: [B*H][512][64], SW128-swizzled 128B rows
__device__ __nv_bfloat16 g_qh[(size_t)BB * HH * LL * HDIM];
__device__ __nv_bfloat16 g_ql[(size_t)BB * HH * LL * HDIM];
__device__ __nv_bfloat16 g_kh[(size_t)BB * HH * LL * HDIM];
__device__ __nv_bfloat16 g_kl[(size_t)BB * HH * LL * HDIM];
__device__ __nv_bfloat16 g_vh[(size_t)BB * HH * LL * HDIM];
__device__ __nv_bfloat16 g_vl[(size_t)BB * HH * LL * HDIM];

// ---------------- PTX helpers ----------------
__device__ __forceinline__ uint32_t smem_u32(const void* p) {
    uint32_t a;
    asm("{ .reg .u64 t; cvta.to.shared.u64 t, %1; cvt.u32.u64 %0, t; }" : "=r"(a) : "l"(p));
    return a;
}

#define MBAR_INIT(a, n) \
    asm volatile("mbarrier.init.shared.b64 [%0], %1;" :: "r"(a), "r"((uint32_t)(n)) : "memory")
#define MBAR_EXPECT_TX(a, b) \
    asm volatile("mbarrier.arrive.expect_tx.shared.b64 _, [%0], %1;" :: "r"(a), "r"((uint32_t)(b)) : "memory")

__device__ __forceinline__ void mbar_wait(uint32_t mbar, uint32_t parity) {
    asm volatile(
        "{\n\t.reg .pred P;\n\t"
        "WL_%=:\n\t"
        "mbarrier.try_wait.parity.acquire.cta.shared::cta.b64 P, [%0], %1, 0x989680;\n\t"
        "@P bra.uni WD_%=;\n\t"
        "bra.uni WL_%=;\n\t"
        "WD_%=:\n\t}"
        :: "r"(mbar), "r"(parity) : "memory");
}

__device__ __forceinline__ void bulk_g2s(uint32_t dst, const void* src, uint32_t bytes, uint32_t mbar) {
    asm volatile(
        "cp.async.bulk.shared::cluster.global.mbarrier::complete_tx::bytes [%0], [%1], %2, [%3];"
        :: "r"(dst), "l"(src), "r"(bytes), "r"(mbar) : "memory");
}

__device__ __forceinline__ void ldsm_x4(uint32_t* r, uint32_t a) {
    asm volatile("ldmatrix.sync.aligned.m8n8.x4.shared.b16 {%0,%1,%2,%3}, [%4];"
                 : "=r"(r[0]), "=r"(r[1]), "=r"(r[2]), "=r"(r[3]) : "r"(a));
}
__device__ __forceinline__ void ldsm_x4t(uint32_t* r, uint32_t a) {
    asm volatile("ldmatrix.sync.aligned.m8n8.x4.trans.shared.b16 {%0,%1,%2,%3}, [%4];"
                 : "=r"(r[0]), "=r"(r[1]), "=r"(r[2]), "=r"(r[3]) : "r"(a));
}
__device__ __forceinline__ void mma_bf16(float* d, const uint32_t* a, const uint32_t* b) {
    asm volatile(
        "mma.sync.aligned.m16n8k16.row.col.f32.bf16.bf16.f32 "
        "{%0,%1,%2,%3}, {%4,%5,%6,%7}, {%8,%9}, {%0,%1,%2,%3};"
        : "+f"(d[0]), "+f"(d[1]), "+f"(d[2]), "+f"(d[3])
        : "r"(a[0]), "r"(a[1]), "r"(a[2]), "r"(a[3]), "r"(b[0]), "r"(b[1]));
}

__device__ __forceinline__ uint32_t pack_bf2(__nv_bfloat16 a, __nv_bfloat16 b) {
    return (uint32_t)__bfloat16_as_ushort(a) | ((uint32_t)__bfloat16_as_ushort(b) << 16);
}

// ---------------- RoPE tables ----------------
__global__ void rope_init_kernel() {
    int idx = blockIdx.x * blockDim.x + threadIdx.x;
    if (idx >= LL * 32) return;
    int l = idx >> 5;
    int jp = idx & 31;
    float inv = 1.0f / powf(10000.0f, (float)(2 * jp) / 64.0f);
    float ang = (float)l * inv;
    g_cos[idx] = cosf(ang);
    g_sin[idx] = sinf(ang);
}

// ---------------- router ----------------
__global__ void router_kernel(const float* __restrict__ x,
                              const float* __restrict__ rw,
                              const float* __restrict__ rb,
                              float* __restrict__ probs_out,
                              int write_probs) {
    int b = blockIdx.x;
    __shared__ float mean[DD];
    __shared__ float logits[EE];

    for (int d = threadIdx.x; d < DD; d += blockDim.x) {
        const float* xp = x + (size_t)b * LL * DD + d;
        float s = 0.f;
        #pragma unroll 8
        for (int l = 0; l < LL; l++) s += xp[(size_t)l * DD];
        mean[d] = s * (1.0f / (float)LL);
    }
    __syncthreads();

    int w = threadIdx.x >> 5;
    int lane = threadIdx.x & 31;
    if (w < EE) {
        float s = 0.f;
        for (int d = lane; d < DD; d += 32) s += mean[d] * rw[d * EE + w];
        #pragma unroll
        for (int o = 16; o > 0; o >>= 1) s += __shfl_down_sync(0xffffffffu, s, o);
        if (lane == 0) logits[w] = s + rb[w];
    }
    __syncthreads();

    if (threadIdx.x == 0) {
        float m = logits[0]; int arg = 0;
        #pragma unroll
        for (int e = 1; e < EE; e++) if (logits[e] > m) { m = logits[e]; arg = e; }
        float p[EE], sum = 0.f;
        #pragma unroll
        for (int e = 0; e < EE; e++) { p[e] = expf(logits[e] - m); sum += p[e]; }
        if (write_probs) {
            float inv = 1.0f / sum;
            #pragma unroll
            for (int e = 0; e < EE; e++) probs_out[b * EE + e] = p[e] * inv;
        }
        g_routes[b] = arg;
    }
}

// ---------------- convert X -> tiled swizzled bf16 hi/lo ----------------
__global__ void convert_x_kernel(const float* __restrict__ src) {
    const int kc = blockIdx.x, rt = blockIdx.y;
    const int t = threadIdx.x;
    const size_t tile_elem = ((size_t)rt * 16 + kc) * 8192;
    char* dh = (char*)(g_xh + tile_elem);
    char* dl = (char*)(g_xl + tile_elem);

    #pragma unroll
    for (int i = 0; i < 4; i++) {
        int u = t + i * 256;             // 0..1023 16B units
        int r = u >> 3, k8 = u & 7;
        const float* p = src + ((size_t)(rt * 128 + r)) * DD + kc * 64 + k8 * 8;
        float4 a = *(const float4*)p;
        float4 b4 = *(const float4*)(p + 4);
        float xs[8] = {a.x, a.y, a.z, a.w, b4.x, b4.y, b4.z, b4.w};
        __nv_bfloat16 hi[8], lo[8];
        #pragma unroll
        for (int j = 0; j < 8; j++) {
            hi[j] = __float2bfloat16(xs[j]);
            lo[j] = __float2bfloat16(xs[j] - __bfloat162float(hi[j]));
        }
        uint32_t off = (uint32_t)(u * 16);
        off ^= (off >> 3) & 0x70;        // SW128
        uint4 hv = make_uint4(pack_bf2(hi[0], hi[1]), pack_bf2(hi[2], hi[3]),
                              pack_bf2(hi[4], hi[5]), pack_bf2(hi[6], hi[7]));
        uint4 lv = make_uint4(pack_bf2(lo[0], lo[1]), pack_bf2(lo[2], lo[3]),
                              pack_bf2(lo[4], lo[5]), pack_bf2(lo[6], lo[7]));
        *(uint4*)(dh + off) = hv;
        *(uint4*)(dl + off) = lv;
    }
}

// ---------------- convert+transpose W (two weight sets per launch) ----------------
__global__ void convert_w_kernel(const float* __restrict__ W0,
                                 const float* __restrict__ W1, int wsel0) {
    __shared__ float sm[64][129];
    const int kc = blockIdx.x, nt = blockIdx.y;
    const int e = blockIdx.z & 7;
    const int which = blockIdx.z >> 3;
    const float* W = which ? W1 : W0;
    const int wsel = wsel0 + which;
    const int t = threadIdx.x;
    const float* src = W + ((size_t)e * DD + kc * 64) * DD + nt * 128;

    #pragma unroll
    for (int i = 0; i < 8; i++) {
        int idx = t + i * 256;           // 0..2047 float4s
        int kr = idx >> 5, nc = (idx & 31) << 2;
        float4 v = *(const float4*)(src + (size_t)kr * DD + nc);
        sm[kr][nc] = v.x; sm[kr][nc + 1] = v.y; sm[kr][nc + 2] = v.z; sm[kr][nc + 3] = v.w;
    }
    __syncthreads();

    const size_t tile_elem = (((size_t)e * 8 + nt) * 16 + kc) * 8192;
    char* dh = (char*)(g_wth + (size_t)wsel * 8388608 + tile_elem);
    char* dl = (char*)(g_wtl + (size_t)wsel * 8388608 + tile_elem);

    #pragma unroll
    for (int i = 0; i < 4; i++) {
        int u = t + i * 256;             // 0..1023
        int n = u >> 3, k8 = u & 7;
        __nv_bfloat16 hi[8], lo[8];
        #pragma unroll
        for (int j = 0; j < 8; j++) {
            float x = sm[k8 * 8 + j][n];
            hi[j] = __float2bfloat16(x);
            lo[j] = __float2bfloat16(x - __bfloat162float(hi[j]));
        }
        uint32_t off = (uint32_t)(u * 16);
        off ^= (off >> 3) & 0x70;
        uint4 hv = make_uint4(pack_bf2(hi[0], hi[1]), pack_bf2(hi[2], hi[3]),
                              pack_bf2(hi[4], hi[5]), pack_bf2(hi[6], hi[7]));
        uint4 lv = make_uint4(pack_bf2(lo[0], lo[1]), pack_bf2(lo[2], lo[3]),
                              pack_bf2(lo[4], lo[5]), pack_bf2(lo[6], lo[7]));
        *(uint4*)(dh + off) = hv;
        *(uint4*)(dl + off) = lv;
    }
}

// ---------------- HMMA GEMM: CTA tile 128x256, warp tile 64x64 (2m x 4n warps) -------
// K=1024 in 16 chunks of 64; 2-stage bulk-copy pipeline (96KB/stage).
// Term-major MMA issue: per accumulator, dependent MMAs are ~16 issues apart.
__global__ void __launch_bounds__(256, 1) hmma_gemm_kernel(float* __restrict__ out, int mode0) {
    extern __shared__ __align__(1024) char smem[];
    const uint32_t sb = smem_u32(smem);
    const int tid = threadIdx.x;
    const int lane = tid & 31, wid = tid >> 5;
    const int wm = wid >> 2, wn = wid & 3;            // 2(m) x 4(n)
    const int nt = blockIdx.x & 3;
    const int mode = mode0 + (blockIdx.x >> 2);
    const int mt = blockIdx.y, b = blockIdx.z;
    const int e = g_routes[b];

    const uint32_t FULLB = sb;                  // 2 mbarriers
    const uint32_t TILES = sb + 1024;           // 2 stages x 96KB
    // stage layout: Ah 0 | Al 16K | Bh0 32K | Bh1 48K | Bl0 64K | Bl1 80K

    if (tid == 0) { MBAR_INIT(FULLB, 1); MBAR_INIT(FULLB + 8, 1); }
    __syncthreads();

    const size_t a_t0 = ((size_t)(b * 4 + mt) * 16) * 8192;
    const __nv_bfloat16* Ah = g_xh + a_t0;
    const __nv_bfloat16* Al = g_xl + a_t0;
    const size_t wb = (size_t)mode * 8388608;
    const size_t b_t0 = (((size_t)e * 8) + 2 * nt) * 16 * 8192;     // tile (2nt, kc=0)
    const __nv_bfloat16* Bh0 = g_wth + wb + b_t0;
    const __nv_bfloat16* Bh1 = Bh0 + (size_t)16 * 8192;             // tile (2nt+1)
    const __nv_bfloat16* Bl0 = g_wtl + wb + b_t0;
    const __nv_bfloat16* Bl1 = Bl0 + (size_t)16 * 8192;

    auto issue = [&](int c) {
        int s = c & 1;
        uint32_t fb = FULLB + s * 8;
        uint32_t st = TILES + s * 98304;
        MBAR_EXPECT_TX(fb, 98304);
        bulk_g2s(st,         Ah  + (size_t)c * 8192, 16384, fb);
        bulk_g2s(st + 16384, Al  + (size_t)c * 8192, 16384, fb);
        bulk_g2s(st + 32768, Bh0 + (size_t)c * 8192, 16384, fb);
        bulk_g2s(st + 49152, Bh1 + (size_t)c * 8192, 16384, fb);
        bulk_g2s(st + 65536, Bl0 + (size_t)c * 8192, 16384, fb);
        bulk_g2s(st + 81920, Bl1 + (size_t)c * 8192, 16384, fb);
    };
    if (tid == 0) { issue(0); issue(1); }

    float acc[4][8][4];
    #pragma unroll
    for (int mf = 0; mf < 4; mf++)
        #pragma unroll
        for (int nf = 0; nf < 8; nf++)
            #pragma unroll
            for (int r = 0; r < 4; r++) acc[mf][nf][r] = 0.f;

    // A ldmatrix address components (per-warp 64 m-rows)
    const uint32_t a_row  = (uint32_t)(wm * 64 + (lane & 15)) * 128;
    const uint32_t a_koff = (uint32_t)(lane >> 4) * 16;
    // B: warp wn covers n 64wn..64wn+63; tile half = wn>>1, row base (wn&1)*64
    const uint32_t b_tile = 32768 + (uint32_t)(wn >> 1) * 16384;
    const uint32_t b_row  = (uint32_t)((wn & 1) * 64 + (lane & 7) + ((lane >> 4) << 3)) * 128;
    const uint32_t b_koff = (uint32_t)((lane >> 3) & 1) * 16;

    for (int c = 0; c < 16; c++) {
        const int s = c & 1;
        mbar_wait(FULLB + s * 8, (uint32_t)((c >> 1) & 1));
        const uint32_t base = TILES + s * 98304;

        #pragma unroll
        for (int ks = 0; ks < 4; ks++) {
            const uint32_t k0b = (uint32_t)ks * 32;
            uint32_t ah[4][4], al[4][4];
            #pragma unroll
            for (int mf = 0; mf < 4; mf++) {
                uint32_t byt = a_row + (uint32_t)mf * 2048 + a_koff + k0b;
                uint32_t sw = byt ^ ((byt >> 3) & 0x70);
                ldsm_x4(ah[mf], base + sw);
                ldsm_x4(al[mf], base + 16384 + sw);
            }
            #pragma unroll
            for (int ph = 0; ph < 2; ph++) {    // process n in halves of 32 cols
                uint32_t bh[2][4], bl[2][4];
                #pragma unroll
                for (int q = 0; q < 2; q++) {
                    const int p = 2 * ph + q;
                    uint32_t byt = b_row + (uint32_t)p * 2048 + b_koff + k0b;
                    uint32_t sw = byt ^ ((byt >> 3) & 0x70);
                    ldsm_x4(bh[q], base + b_tile + sw);
                    ldsm_x4(bl[q], base + b_tile + 32768 + sw);
                }
                // term 1: hi*hi (16 independent accumulators)
                #pragma unroll
                for (int q = 0; q < 2; q++) {
                    const int p = 2 * ph + q;
                    #pragma unroll
                    for (int mf = 0; mf < 4; mf++) {
                        mma_bf16(acc[mf][2 * p],     ah[mf], &bh[q][0]);
                        mma_bf16(acc[mf][2 * p + 1], ah[mf], &bh[q][2]);
                    }
                }
                // term 2: hi*lo
                #pragma unroll
                for (int q = 0; q < 2; q++) {
                    const int p = 2 * ph + q;
                    #pragma unroll
                    for (int mf = 0; mf < 4; mf++) {
                        mma_bf16(acc[mf][2 * p],     ah[mf], &bl[q][0]);
                        mma_bf16(acc[mf][2 * p + 1], ah[mf], &bl[q][2]);
                    }
                }
                // term 3: lo*hi
                #pragma unroll
                for (int q = 0; q < 2; q++) {
                    const int p = 2 * ph + q;
                    #pragma unroll
                    for (int mf = 0; mf < 4; mf++) {
                        mma_bf16(acc[mf][2 * p],     al[mf], &bh[q][0]);
                        mma_bf16(acc[mf][2 * p + 1], al[mf], &bh[q][2]);
                    }
                }
            }
        }
        __syncthreads();
        if (tid == 0 && c + 2 < 16) issue(c + 2);
    }

    // ---------------- epilogue ----------------
    const int l_base = mt * 128 + wm * 64 + (lane >> 2);
    const int tig = lane & 3;
    const int hglob = nt * 4 + wn;               // whole warp same 64-col group

    #pragma unroll
    for (int mf = 0; mf < 4; mf++) {
        #pragma unroll
        for (int rh = 0; rh < 2; rh++) {
            const int l = l_base + mf * 16 + 8 * rh;
            #pragma unroll
            for (int nf = 0; nf < 8; nf++) {
                const int d = 8 * nf + 2 * tig;
                float x0 = acc[mf][nf][2 * rh];
                float x1 = acc[mf][nf][2 * rh + 1];
                if (mode == 3) {
                    float2* dst = (float2*)(out + ((size_t)b * LL + l) * DD + hglob * 64 + d);
                    *dst = make_float2(x0, x1);
                } else {
                    float y0, y1;
                    if (mode == 2) { y0 = x0; y1 = x1; }
                    else {
                        const int p = d >> 1;
                        float cs = g_cos[l * 32 + p];
                        float sn = g_sin[l * 32 + p];
                        y0 = x0 * cs - x1 * sn;
                        y1 = x1 * cs + x0 * sn;
                    }
                    __nv_bfloat16 hb0 = __float2bfloat16(y0);
                    __nv_bfloat16 hb1 = __float2bfloat16(y1);
                    __nv_bfloat16 lb0 = __float2bfloat16(y0 - __bfloat162float(hb0));
                    __nv_bfloat16 lb1 = __float2bfloat16(y1 - __bfloat162float(hb1));
                    uint32_t off = (uint32_t)((((b * HH + hglob) * LL) + l) * 128 + d * 2);
                    uint32_t sw = off ^ ((off >> 3) & 0x70);
                    char* bhp = (char*)((mode == 0) ? g_qh : (mode == 1) ? g_kh : g_vh);
                    char* blp = (char*)((mode == 0) ? g_ql : (mode == 1) ? g_kl : g_vl);
                    *(uint32_t*)(bhp + sw) = pack_bf2(hb0, hb1);
                    *(uint32_t*)(blp + sw) = pack_bf2(lb0, lb1);
                }
            }
        }
    }
}

// ---------------- flash attention on HMMA: 128 q-rows/CTA, 8 warps x 16 rows ---------
__global__ void __launch_bounds__(256, 2) attn_kernel() {
    extern __shared__ __align__(1024) char smem[];
    const uint32_t sb = smem_u32(smem);
    const int tid = threadIdx.x, lane = tid & 31, w = tid >> 5;
    const int qt = 3 - blockIdx.x;       // long CTAs first
    const int bh = blockIdx.y;
    const int b = bh >> 4, h = bh & 15;
    const int g = lane >> 2, tig = lane & 3;

    const uint32_t QB = sb;              // Q mbarrier
    const uint32_t FB = sb + 8;          // kv full barriers: stage0 @+8, stage1 @+16
    const uint32_t QT = sb + 1024;       // Q hi 16KB | Q lo 16KB
    const uint32_t KV = sb + 1024 + 32768; // 2 stages x (Kh|Kl|Vh|Vl each 8KB)

    if (tid == 0) { MBAR_INIT(QB, 1); MBAR_INIT(FB, 1); MBAR_INIT(FB + 8, 1); }
    __syncthreads();

    const size_t bh_off = (size_t)bh * LL * HDIM;
    const __nv_bfloat16* kh = g_kh + bh_off;
    const __nv_bfloat16* kl = g_kl + bh_off;
    const __nv_bfloat16* vh = g_vh + bh_off;
    const __nv_bfloat16* vl = g_vl + bh_off;

    const int jmax = 2 * qt + 2;

    auto issue = [&](int jt) {
        int s = jt & 1;
        uint32_t fb = FB + s * 8;
        uint32_t st = KV + s * 32768;
        MBAR_EXPECT_TX(fb, 32768);
        bulk_g2s(st,         kh + (size_t)jt * 4096, 8192, fb);
        bulk_g2s(st + 8192,  kl + (size_t)jt * 4096, 8192, fb);
        bulk_g2s(st + 16384, vh + (size_t)jt * 4096, 8192, fb);
        bulk_g2s(st + 24576, vl + (size_t)jt * 4096, 8192, fb);
    };
    if (tid == 0) {
        MBAR_EXPECT_TX(QB, 32768);
        bulk_g2s(QT,         g_qh + bh_off + (size_t)qt * 128 * 64, 16384, QB);
        bulk_g2s(QT + 16384, g_ql + bh_off + (size_t)qt * 128 * 64, 16384, QB);
        issue(0);
        issue(1);
    }

    float o[8][4];
    #pragma unroll
    for (int nf = 0; nf < 8; nf++)
        #pragma unroll
        for (int r = 0; r < 4; r++) o[nf][r] = 0.f;
    float m0 = -1e30f, m1 = -1e30f, l0 = 0.f, l1 = 0.f;

    const int rowmin = qt * 128 + w * 16;

    mbar_wait(QB, 0);

    for (int jt = 0; jt < jmax; jt++) {
        const int s = jt & 1;
        mbar_wait(FB + s * 8, (uint32_t)((jt >> 1) & 1));
        const uint32_t kb = KV + s * 32768;

        if (jt * 64 <= rowmin + 15) {      // not fully masked for this warp
            float p[8][4];
            #pragma unroll
            for (int nf = 0; nf < 8; nf++)
                #pragma unroll
                for (int r = 0; r < 4; r++) p[nf][r] = 0.f;

            // S = Q K^T (3-term split)
            #pragma unroll
            for (int ks = 0; ks < 4; ks++) {
                uint32_t qoff = (uint32_t)(w * 16 + (lane & 15)) * 128
                                + (uint32_t)(lane >> 4) * 16 + (uint32_t)ks * 32;
                uint32_t swq = qoff ^ ((qoff >> 3) & 0x70);
                uint32_t ah[4], al[4];
                ldsm_x4(ah, QT + swq);
                ldsm_x4(al, QT + 16384 + swq);
                #pragma unroll
                for (int nfp = 0; nfp < 4; nfp++) {
                    uint32_t koff = (uint32_t)(nfp * 16 + (lane & 7) + ((lane & 16) >> 1)) * 128
                                    + (uint32_t)ks * 32 + ((lane & 8) << 1);
                    uint32_t swk = koff ^ ((koff >> 3) & 0x70);
                    uint32_t kbh[4], kbl[4];
                    ldsm_x4(kbh, kb + swk);
                    ldsm_x4(kbl, kb + 8192 + swk);
                    mma_bf16(p[2 * nfp],     ah, &kbh[0]);
                    mma_bf16(p[2 * nfp],     ah, &kbl[0]);
                    mma_bf16(p[2 * nfp],     al, &kbh[0]);
                    mma_bf16(p[2 * nfp + 1], ah, &kbh[2]);
                    mma_bf16(p[2 * nfp + 1], ah, &kbl[2]);
                    mma_bf16(p[2 * nfp + 1], al, &kbh[2]);
                }
            }

            // scale + causal mask
            const bool need_mask = (jt * 64 + 63) > rowmin;
            #pragma unroll
            for (int nf = 0; nf < 8; nf++)
                #pragma unroll
                for (int r = 0; r < 4; r++) {
                    float v = p[nf][r] * 0.125f;
                    if (need_mask) {
                        int qr = rowmin + g + ((r & 2) << 2);
                        int kc = jt * 64 + 8 * nf + 2 * tig + (r & 1);
                        if (kc > qr) v = -1e30f;
                    }
                    p[nf][r] = v;
                }

            // online softmax
            float mx0 = m0, mx1 = m1;
            #pragma unroll
            for (int nf = 0; nf < 8; nf++) {
                mx0 = fmaxf(mx0, fmaxf(p[nf][0], p[nf][1]));
                mx1 = fmaxf(mx1, fmaxf(p[nf][2], p[nf][3]));
            }
            mx0 = fmaxf(mx0, __shfl_xor_sync(0xffffffffu, mx0, 1));
            mx0 = fmaxf(mx0, __shfl_xor_sync(0xffffffffu, mx0, 2));
            mx1 = fmaxf(mx1, __shfl_xor_sync(0xffffffffu, mx1, 1));
            mx1 = fmaxf(mx1, __shfl_xor_sync(0xffffffffu, mx1, 2));
            float c0 = __expf(m0 - mx0), c1 = __expf(m1 - mx1);
            m0 = mx0; m1 = mx1;
            float s0 = 0.f, s1 = 0.f;
            #pragma unroll
            for (int nf = 0; nf < 8; nf++) {
                p[nf][0] = __expf(p[nf][0] - mx0); s0 += p[nf][0];
                p[nf][1] = __expf(p[nf][1] - mx0); s0 += p[nf][1];
                p[nf][2] = __expf(p[nf][2] - mx1); s1 += p[nf][2];
                p[nf][3] = __expf(p[nf][3] - mx1); s1 += p[nf][3];
            }
            s0 += __shfl_xor_sync(0xffffffffu, s0, 1);
            s0 += __shfl_xor_sync(0xffffffffu, s0, 2);
            s1 += __shfl_xor_sync(0xffffffffu, s1, 1);
            s1 += __shfl_xor_sync(0xffffffffu, s1, 2);
            l0 = l0 * c0 + s0;
            l1 = l1 * c1 + s1;
            #pragma unroll
            for (int nf = 0; nf < 8; nf++) {
                o[nf][0] *= c0; o[nf][1] *= c0;
                o[nf][2] *= c1; o[nf][3] *= c1;
            }

            // O += P V (3-term split; P C-frags -> A-frags in registers)
            #pragma unroll
            for (int j = 0; j < 4; j++) {
                uint32_t pah[4], pal[4];
                #pragma unroll
                for (int half = 0; half < 2; half++) {
                    const float* pf = p[2 * j + half];
                    __nv_bfloat16 h0 = __float2bfloat16(pf[0]);
                    __nv_bfloat16 h1 = __float2bfloat16(pf[1]);
                    __nv_bfloat16 h2 = __float2bfloat16(pf[2]);
                    __nv_bfloat16 h3 = __float2bfloat16(pf[3]);
                    pah[2 * half]     = pack_bf2(h0, h1);
                    pah[2 * half + 1] = pack_bf2(h2, h3);
                    pal[2 * half]     = pack_bf2(__float2bfloat16(pf[0] - __bfloat162float(h0)),
                                                 __float2bfloat16(pf[1] - __bfloat162float(h1)));
                    pal[2 * half + 1] = pack_bf2(__float2bfloat16(pf[2] - __bfloat162float(h2)),
                                                 __float2bfloat16(pf[3] - __bfloat162float(h3)));
                }
                #pragma unroll
                for (int nfp = 0; nfp < 4; nfp++) {
                    uint32_t voff = (uint32_t)(16 * j + (lane & 7) + (lane & 8)) * 128
                                    + (uint32_t)nfp * 32 + (lane & 16);
                    uint32_t swv = voff ^ ((voff >> 3) & 0x70);
                    uint32_t vbh[4], vbl[4];
                    ldsm_x4t(vbh, kb + 16384 + swv);
                    ldsm_x4t(vbl, kb + 24576 + swv);
                    mma_bf16(o[2 * nfp],     pah, &vbh[0]);
                    mma_bf16(o[2 * nfp],     pah, &vbl[0]);
                    mma_bf16(o[2 * nfp],     pal, &vbh[0]);
                    mma_bf16(o[2 * nfp + 1], pah, &vbh[2]);
                    mma_bf16(o[2 * nfp + 1], pah, &vbl[2]);
                    mma_bf16(o[2 * nfp + 1], pal, &vbh[2]);
                }
            }
        }
        __syncthreads();
        if (tid == 0 && jt + 2 < jmax) issue(jt + 2);
    }

    // epilogue: O /= l; write AO as hi/lo swizzled tile (rt = b*4+qt, kc = h)
    const float i0 = 1.f / l0, i1 = 1.f / l1;
    const size_t tb = (((size_t)(b * 4 + qt) * 16) + h) * 16384;   // bytes
    char* dh = (char*)g_xh + tb;
    char* dl = (char*)g_xl + tb;
    #pragma unroll
    for (int nf = 0; nf < 8; nf++) {
        #pragma unroll
        for (int rh = 0; rh < 2; rh++) {
            float y0 = o[nf][2 * rh]     * (rh ? i1 : i0);
            float y1 = o[nf][2 * rh + 1] * (rh ? i1 : i0);
            __nv_bfloat16 hb0 = __float2bfloat16(y0);
            __nv_bfloat16 hb1 = __float2bfloat16(y1);
            __nv_bfloat16 lb0 = __float2bfloat16(y0 - __bfloat162float(hb0));
            __nv_bfloat16 lb1 = __float2bfloat16(y1 - __bfloat162float(hb1));
            uint32_t off = (uint32_t)((w * 16 + g + 8 * rh) * 128 + (8 * nf + 2 * tig) * 2);
            uint32_t sw = off ^ ((off >> 3) & 0x70);
            *(uint32_t*)(dh + sw) = pack_bf2(hb0, hb1);
            *(uint32_t*)(dl + sw) = pack_bf2(lb0, lb1);
        }
    }
}

// ---------------- launch ----------------
extern "C" void kernel_launch(void* const* d_in, const int* in_sizes, int n_in,
                              void* d_out, int out_size) {
    const float* x  = (const float*)d_in[0];
    const float* qw = (const float*)d_in[1];
    const float* kw = (const float*)d_in[2];
    const float* vw = (const float*)d_in[3];
    const float* ow = (const float*)d_in[4];
    const float* rw = (const float*)d_in[5];
    const float* rb = (const float*)d_in[6];
    float* out = (float*)d_out;

    const int GEMM_SMEM = 1024 + 2 * 98304;   // 197632
    cudaFuncSetAttribute(hmma_gemm_kernel, cudaFuncAttributeMaxDynamicSharedMemorySize, GEMM_SMEM);
    const int ATTN_SMEM = 1024 + 32768 + 2 * 32768;   // 99328
    cudaFuncSetAttribute(attn_kernel, cudaFuncAttributeMaxDynamicSharedMemorySize, ATTN_SMEM);

    // launch order matters for ncu (-s 5 -c 1 captures launch index 5 = QKV GEMM)
    rope_init_kernel<<<(LL * 32 + 255) / 256, 256>>>();                       // 0

    int write_probs = (out_size >= BB * LL * DD + BB * EE) ? 1 : 0;
    router_kernel<<<BB, 256>>>(x, rw, rb, out + (size_t)BB * LL * DD, write_probs); // 1

    convert_x_kernel<<<dim3(16, 128), 256>>>(x);                              // 2
    convert_w_kernel<<<dim3(16, 8, 16), 256>>>(qw, kw, 0);                    // 3
    convert_w_kernel<<<dim3(16, 8, 16), 256>>>(vw, ow, 2);                    // 4

    // fused Q/K/V projection: grid.x = 4 nt * 3 modes
    hmma_gemm_kernel<<<dim3(12, 4, BB), 256, GEMM_SMEM>>>(nullptr, 0);        // 5 <- profiled

    attn_kernel<<<dim3(4, BB * HH), 256, ATTN_SMEM>>>();                      // 6

    // out projection
    hmma_gemm_kernel<<<dim3(4, 4, BB), 256, GEMM_SMEM>>>(out, 3);             // 7
}